// round 10
// baseline (speedup 1.0000x reference)
#include <cuda_runtime.h>
#include <cuda_bf16.h>
#include <cstdint>

#define NN 100000
#define EE 3200000
#define XDIM 256
#define HDIM 128
#define GDIM 128
#define DDIM 257
#define NB 391        // ceil(NN/256)
#define KPAD 288      // padded K for head GEMM (9 x 32)
#define NPAD 320      // padded N (5 x 64)
#define KCH 9

// ---------- scratch (device globals; no allocation allowed) ----------
__device__ float g_h[(size_t)NN * HDIM];
__device__ int   g_cnt[NN];
__device__ int   g_rowptr[NN + 1];
__device__ int   g_woff[NN];
__device__ int   g_csr[EE];
__device__ float g_dis[NN];
__device__ int   g_blksum[512];
__device__ __nv_bfloat16 g_rep_hi[(size_t)NN * KPAD];
__device__ __nv_bfloat16 g_rep_lo[(size_t)NN * KPAD];
__device__ __nv_bfloat16 g_wt[2][2][NPAD * KPAD];   // [head][hi/lo][n*KPAD+k]

// ---------- helpers ----------
__device__ __forceinline__ uint32_t smem_u32(const void* p) {
    uint32_t a;
    asm("{ .reg .u64 t; cvta.to.shared.u64 t, %1; cvt.u32.u64 %0, t; }"
        : "=r"(a) : "l"(p));
    return a;
}
__device__ __forceinline__ void ffma2(unsigned long long& d,
                                      unsigned long long a,
                                      unsigned long long b)
{
    asm("fma.rn.f32x2 %0, %1, %2, %3;" : "=l"(d) : "l"(a), "l"(b), "l"(d));
}
__device__ __forceinline__ void ldm_x4(uint32_t& r0, uint32_t& r1,
                                       uint32_t& r2, uint32_t& r3, uint32_t addr)
{
    asm volatile("ldmatrix.sync.aligned.m8n8.x4.shared.b16 {%0,%1,%2,%3}, [%4];"
        : "=r"(r0), "=r"(r1), "=r"(r2), "=r"(r3) : "r"(addr));
}
__device__ __forceinline__ void mma_bf16(float* c, const uint32_t* a,
                                         uint32_t b0, uint32_t b1)
{
    asm volatile("mma.sync.aligned.m16n8k16.row.col.f32.bf16.bf16.f32 "
        "{%0,%1,%2,%3}, {%4,%5,%6,%7}, {%8,%9}, {%0,%1,%2,%3};"
        : "+f"(c[0]), "+f"(c[1]), "+f"(c[2]), "+f"(c[3])
        : "r"(a[0]), "r"(a[1]), "r"(a[2]), "r"(a[3]), "r"(b0), "r"(b1));
}
__device__ __forceinline__ void bf16split(float x, __nv_bfloat16& hi, __nv_bfloat16& lo) {
    hi = __float2bfloat16(x);
    lo = __float2bfloat16(x - __bfloat162float(hi));
}

// ---------- kernel 0: zero degree counters ----------
__global__ void k_zero()
{
    int i = blockIdx.x * blockDim.x + threadIdx.x;
    if (i < NN) g_cnt[i] = 0;
}

// ---------- kernel 1: fused phi (FFMA2) + bf16 split of phi cols ----------
#define PHI_SMEM 83456
__global__ __launch_bounds__(256) void k_phi(
    const float* __restrict__ X, const float* __restrict__ T,
    const float* __restrict__ Wphi, const float* __restrict__ bphi,
    const float* __restrict__ Wgcn, float* __restrict__ out_rep)
{
    extern __shared__ float psm[];
    float* sXT = psm;             // [32][130]  phase1 A^T
    float* sW  = psm + 4160;      // [32][132]  phase1 W
    float* sPT = psm;             // [128][130] phase2 (T*phi)^T
    float* sWg = psm + 16640;     // [32][132]  phase2 W

    const int row0 = blockIdx.x * 128;
    const int t  = threadIdx.x;
    const int r0 = (t >> 5) * 16;
    const int c0 = (t & 31) * 4;

    unsigned long long acc2[8][4];
#pragma unroll
    for (int p = 0; p < 8; p++)
#pragma unroll
        for (int j = 0; j < 4; j++) acc2[p][j] = 0ull;

    // ---- phase 1: phi = X @ Wphi (K = 256) ----
    for (int k0 = 0; k0 < XDIM; k0 += 32) {
#pragma unroll
        for (int it = 0; it < 16; it++) {
            int q = t + it * 256;
            int r = q >> 5, kk = q & 31;
            int grow = row0 + r;
            sXT[kk * 130 + r] = (grow < NN) ? X[(size_t)grow * XDIM + k0 + kk] : 0.f;
        }
#pragma unroll
        for (int it = 0; it < 16; it++) {
            int q = t + it * 256;
            int kr = q >> 7, c = q & 127;
            sW[kr * 132 + c] = Wphi[(size_t)(k0 + kr) * HDIM + c];
        }
        __syncthreads();
#pragma unroll
        for (int kk = 0; kk < 32; kk++) {
            unsigned long long a2[8];
#pragma unroll
            for (int p = 0; p < 8; p++)
                a2[p] = *(const unsigned long long*)&sXT[kk * 130 + r0 + 2 * p];
            float4 w4 = *(const float4*)&sW[kk * 132 + c0];
            unsigned long long w2[4];
            asm("mov.b64 %0, {%1, %1};" : "=l"(w2[0]) : "f"(w4.x));
            asm("mov.b64 %0, {%1, %1};" : "=l"(w2[1]) : "f"(w4.y));
            asm("mov.b64 %0, {%1, %1};" : "=l"(w2[2]) : "f"(w4.z));
            asm("mov.b64 %0, {%1, %1};" : "=l"(w2[3]) : "f"(w4.w));
#pragma unroll
            for (int p = 0; p < 8; p++)
#pragma unroll
                for (int j = 0; j < 4; j++)
                    ffma2(acc2[p][j], a2[p], w2[j]);
        }
        __syncthreads();
    }

    // ---- epilogue 1: relu+bias -> rep (+bf16 split); T*phi -> sPT ----
#pragma unroll
    for (int p = 0; p < 8; p++) {
        int rA = r0 + 2 * p, rB = rA + 1;
        int gA = row0 + rA, gB = row0 + rB;
        float tA = (gA < NN) ? T[gA] : 0.f;
        float tB = (gB < NN) ? T[gB] : 0.f;
#pragma unroll
        for (int j = 0; j < 4; j++) {
            union { unsigned long long u; float2 f; } cv;
            cv.u = acc2[p][j];
            int c = c0 + j;
            float bb = bphi[c];
            float pA = fmaxf(cv.f.x + bb, 0.f);
            float pB = fmaxf(cv.f.y + bb, 0.f);
            __nv_bfloat16 hi, lo;
            if (gA < NN) {
                out_rep[(size_t)gA * DDIM + c] = pA;
                bf16split(pA, hi, lo);
                g_rep_hi[(size_t)gA * KPAD + c] = hi;
                g_rep_lo[(size_t)gA * KPAD + c] = lo;
            }
            if (gB < NN) {
                out_rep[(size_t)gB * DDIM + c] = pB;
                bf16split(pB, hi, lo);
                g_rep_hi[(size_t)gB * KPAD + c] = hi;
                g_rep_lo[(size_t)gB * KPAD + c] = lo;
            }
            sPT[c * 130 + rA] = pA * tA;
            sPT[c * 130 + rB] = pB * tB;
            acc2[p][j] = 0ull;
        }
    }
    __syncthreads();

    // ---- phase 2: h = (T*phi) @ Wgcn (K = 128) ----
    for (int k0 = 0; k0 < HDIM; k0 += 32) {
#pragma unroll
        for (int it = 0; it < 16; it++) {
            int q = t + it * 256;
            int kr = q >> 7, c = q & 127;
            sWg[kr * 132 + c] = Wgcn[(size_t)(k0 + kr) * GDIM + c];
        }
        __syncthreads();
#pragma unroll
        for (int kk = 0; kk < 32; kk++) {
            unsigned long long a2[8];
#pragma unroll
            for (int p = 0; p < 8; p++)
                a2[p] = *(const unsigned long long*)&sPT[(k0 + kk) * 130 + r0 + 2 * p];
            float4 w4 = *(const float4*)&sWg[kk * 132 + c0];
            unsigned long long w2[4];
            asm("mov.b64 %0, {%1, %1};" : "=l"(w2[0]) : "f"(w4.x));
            asm("mov.b64 %0, {%1, %1};" : "=l"(w2[1]) : "f"(w4.y));
            asm("mov.b64 %0, {%1, %1};" : "=l"(w2[2]) : "f"(w4.z));
            asm("mov.b64 %0, {%1, %1};" : "=l"(w2[3]) : "f"(w4.w));
#pragma unroll
            for (int p = 0; p < 8; p++)
#pragma unroll
                for (int j = 0; j < 4; j++)
                    ffma2(acc2[p][j], a2[p], w2[j]);
        }
        __syncthreads();
    }

#pragma unroll
    for (int p = 0; p < 8; p++) {
        int gA = row0 + r0 + 2 * p, gB = gA + 1;
#pragma unroll
        for (int j = 0; j < 4; j++) {
            union { unsigned long long u; float2 f; } cv;
            cv.u = acc2[p][j];
            int c = c0 + j;
            if (gA < NN) g_h[(size_t)gA * GDIM + c] = cv.f.x;
            if (gB < NN) g_h[(size_t)gB * GDIM + c] = cv.f.y;
        }
    }
}

// ---------- count in-degree ----------
__global__ void k_edge1(const int* __restrict__ ei)
{
    int e = blockIdx.x * blockDim.x + threadIdx.x;
    if (e >= EE) return;
    atomicAdd(&g_cnt[ei[EE + e]], 1);
}

// ---------- scan step 1 ----------
__global__ void k_blocksum()
{
    __shared__ int sm[8];
    int t = threadIdx.x;
    int i = blockIdx.x * 256 + t;
    int v = (i < NN) ? g_cnt[i] : 0;
#pragma unroll
    for (int off = 16; off >= 1; off >>= 1)
        v += __shfl_xor_sync(0xffffffffu, v, off);
    if ((t & 31) == 0) sm[t >> 5] = v;
    __syncthreads();
    if (t == 0) {
        int s = 0;
#pragma unroll
        for (int w = 0; w < 8; w++) s += sm[w];
        g_blksum[blockIdx.x] = s;
    }
}

// ---------- scan step 2 ----------
__global__ void k_scanblk()
{
    __shared__ int s[512];
    int t = threadIdx.x;
    int v = (t < NB) ? g_blksum[t] : 0;
    s[t] = v;
    __syncthreads();
    for (int off = 1; off < 512; off <<= 1) {
        int x = (t >= off) ? s[t - off] : 0;
        __syncthreads();
        s[t] += x;
        __syncthreads();
    }
    if (t < NB) g_blksum[t] = s[t] - v;
}

// ---------- scan step 3: rowptr + woff + dis + y bias init ----------
__global__ void k_rowptr(const float* __restrict__ b01, const float* __restrict__ b11,
                         float* __restrict__ y0, float* __restrict__ y1)
{
    __shared__ int s[256];
    int t = threadIdx.x;
    int i = blockIdx.x * 256 + t;
    int v = (i < NN) ? g_cnt[i] : 0;
    s[t] = v;
    __syncthreads();
    for (int off = 1; off < 256; off <<= 1) {
        int x = (t >= off) ? s[t - off] : 0;
        __syncthreads();
        s[t] += x;
        __syncthreads();
    }
    int incl = s[t];
    int base = g_blksum[blockIdx.x];
    if (i < NN) {
        int e = base + incl - v;
        g_rowptr[i] = e;
        g_woff[i]   = e;
        g_dis[i]    = rsqrtf((float)v + 1.0f);
        y0[i] = b01[0];
        y1[i] = b11[0];
    }
    if (i == NN - 1) g_rowptr[NN] = base + incl;
}

// ---------- scatter into CSR ----------
__global__ void k_scatter(const int* __restrict__ ei)
{
    int e = blockIdx.x * blockDim.x + threadIdx.x;
    if (e >= EE) return;
    int s = ei[e];
    int d = ei[EE + e];
    int pos = atomicAdd(&g_woff[d], 1);
    g_csr[pos] = s;
}

// ---------- warp-per-node gather: rep_gnn + z (+bf16 split cols 128..287) ----------
__global__ __launch_bounds__(256) void k_gather(
    const float* __restrict__ T, const float* __restrict__ bgcn,
    float* __restrict__ rep)
{
    int w = (blockIdx.x * 256 + threadIdx.x) >> 5;
    int lane = threadIdx.x & 31;
    if (w >= NN) return;
    int start = g_rowptr[w];
    int end   = g_rowptr[w + 1];
    float disd = g_dis[w];

    float4 acc = make_float4(0.f, 0.f, 0.f, 0.f);
    float zs = 0.f;
    int i = start;
    for (; i + 1 < end; i += 2) {
        int s0 = g_csr[i];
        int s1 = g_csr[i + 1];
        float cf0 = g_dis[s0] * disd;
        float cf1 = g_dis[s1] * disd;
        float4 h0 = *(const float4*)&g_h[(size_t)s0 * GDIM + lane * 4];
        float4 h1 = *(const float4*)&g_h[(size_t)s1 * GDIM + lane * 4];
        acc.x = fmaf(cf0, h0.x, acc.x); acc.x = fmaf(cf1, h1.x, acc.x);
        acc.y = fmaf(cf0, h0.y, acc.y); acc.y = fmaf(cf1, h1.y, acc.y);
        acc.z = fmaf(cf0, h0.z, acc.z); acc.z = fmaf(cf1, h1.z, acc.z);
        acc.w = fmaf(cf0, h0.w, acc.w); acc.w = fmaf(cf1, h1.w, acc.w);
        zs += T[s0] + T[s1];
    }
    if (i < end) {
        int s0 = g_csr[i];
        float cf0 = g_dis[s0] * disd;
        float4 h0 = *(const float4*)&g_h[(size_t)s0 * GDIM + lane * 4];
        acc.x = fmaf(cf0, h0.x, acc.x);
        acc.y = fmaf(cf0, h0.y, acc.y);
        acc.z = fmaf(cf0, h0.z, acc.z);
        acc.w = fmaf(cf0, h0.w, acc.w);
        zs += T[s0];
    }

    int cnt = end - start;
    float invd = 1.0f / ((float)cnt + 1.0f);
    float4 hd = *(const float4*)&g_h[(size_t)w * GDIM + lane * 4];
    int cb = lane * 4;
    float v0 = fmaxf(fmaf(hd.x, invd, acc.x) + bgcn[cb + 0], 0.f);
    float v1 = fmaxf(fmaf(hd.y, invd, acc.y) + bgcn[cb + 1], 0.f);
    float v2 = fmaxf(fmaf(hd.z, invd, acc.z) + bgcn[cb + 2], 0.f);
    float v3 = fmaxf(fmaf(hd.w, invd, acc.w) + bgcn[cb + 3], 0.f);
    float* o = &rep[(size_t)w * DDIM + 128 + cb];
    o[0] = v0; o[1] = v1; o[2] = v2; o[3] = v3;

    // bf16 split -> cols 128..255
    __nv_bfloat16 h4[4], l4[4];
    bf16split(v0, h4[0], l4[0]);
    bf16split(v1, h4[1], l4[1]);
    bf16split(v2, h4[2], l4[2]);
    bf16split(v3, h4[3], l4[3]);
    *(uint2*)&g_rep_hi[(size_t)w * KPAD + 128 + cb] = *(uint2*)h4;
    *(uint2*)&g_rep_lo[(size_t)w * KPAD + 128 + cb] = *(uint2*)l4;

    if (lane == 0) {
        float z = zs / fmaxf((float)cnt, 1.0f);
        rep[(size_t)w * DDIM + 256] = z;
        __nv_bfloat16 zh, zl;
        bf16split(z, zh, zl);
        g_rep_hi[(size_t)w * KPAD + 256] = zh;
        g_rep_lo[(size_t)w * KPAD + 256] = zl;
    } else {
        // zero pad cols 257..287
        g_rep_hi[(size_t)w * KPAD + 256 + lane] = __float2bfloat16(0.f);
        g_rep_lo[(size_t)w * KPAD + 256 + lane] = __float2bfloat16(0.f);
    }
}

// ---------- bf16 split of W00/W10 transposed ----------
__global__ void k_cvt_w(const float* __restrict__ W00, const float* __restrict__ W10)
{
    int idx = blockIdx.x * 256 + threadIdx.x;
    if (idx >= 2 * NPAD * KPAD) return;
    int head = idx / (NPAD * KPAD);
    int rem = idx - head * (NPAD * KPAD);
    int n = rem / KPAD, k = rem - n * KPAD;
    const float* W = head ? W10 : W00;
    float x = (n < DDIM && k < DDIM) ? W[(size_t)k * DDIM + n] : 0.f;
    __nv_bfloat16 hi, lo;
    bf16split(x, hi, lo);
    g_wt[head][0][rem] = hi;
    g_wt[head][1][rem] = lo;
}

// ---------- head GEMM: BOTH heads per CTA, mma.sync bf16 3-pass, reg prefetch ----
// CTA tile 128x64, warp tile 32x32, k-chunks of 32, 2-stage smem (80B pitch)
// stage layout: A_hi @0 (10240), A_lo @10240, B0_hi @20480 (5120), B0_lo @25600,
//               B1_hi @30720, B1_lo @35840
#define STG 40960
#define HEAD_SMEM (2 * STG)
__global__ __launch_bounds__(256) void k_head_mma(
    const float* __restrict__ b00, const float* __restrict__ b10,
    const float* __restrict__ W01, const float* __restrict__ W11,
    float* __restrict__ y0, float* __restrict__ y1)
{
    extern __shared__ char hsm[];
    uint32_t sb = smem_u32(hsm);
    const int tid = threadIdx.x, lane = tid & 31, wid = tid >> 5;
    const int wm = wid & 3, wn = wid >> 2;
    const int row0 = blockIdx.x * 128;
    const int col0 = blockIdx.y * 64;

    // per-thread load coordinates (fixed across chunks)
    const int ar0 = tid >> 2, av = tid & 3;       // A row / vec (it=0)
    const int ar1 = (tid + 256) >> 2;             // A row (it=1)
    const int bn = tid >> 2, bv = tid & 3;        // B n-row / vec
    const int okA0 = (row0 + ar0) < NN;
    const int okA1 = (row0 + ar1) < NN;
    const size_t gaoff0 = (size_t)(row0 + (okA0 ? ar0 : 0)) * KPAD + av * 8;
    const size_t gaoff1 = (size_t)(row0 + (okA1 ? ar1 : 0)) * KPAD + av * 8;
    const size_t gboff  = (size_t)(col0 + bn) * KPAD + bv * 8;

    float acc[2][2][4][4];   // [head][mt][nt][4]
#pragma unroll
    for (int hh = 0; hh < 2; hh++)
#pragma unroll
        for (int mt = 0; mt < 2; mt++)
#pragma unroll
            for (int nt = 0; nt < 4; nt++)
#pragma unroll
                for (int j = 0; j < 4; j++) acc[hh][mt][nt][j] = 0.f;

    uint4 pf[8];
    auto prefetch = [&](int kc) {
        int kbase = kc * 32;
        pf[0] = okA0 ? *(const uint4*)&g_rep_hi[gaoff0 + kbase] : make_uint4(0,0,0,0);
        pf[1] = okA0 ? *(const uint4*)&g_rep_lo[gaoff0 + kbase] : make_uint4(0,0,0,0);
        pf[2] = okA1 ? *(const uint4*)&g_rep_hi[gaoff1 + kbase] : make_uint4(0,0,0,0);
        pf[3] = okA1 ? *(const uint4*)&g_rep_lo[gaoff1 + kbase] : make_uint4(0,0,0,0);
        pf[4] = *(const uint4*)&g_wt[0][0][gboff + kbase];
        pf[5] = *(const uint4*)&g_wt[0][1][gboff + kbase];
        pf[6] = *(const uint4*)&g_wt[1][0][gboff + kbase];
        pf[7] = *(const uint4*)&g_wt[1][1][gboff + kbase];
    };
    auto stage_store = [&](char* base) {
        *(uint4*)(base + ar0 * 80 + av * 16)         = pf[0];
        *(uint4*)(base + 10240 + ar0 * 80 + av * 16) = pf[1];
        *(uint4*)(base + ar1 * 80 + av * 16)         = pf[2];
        *(uint4*)(base + 10240 + ar1 * 80 + av * 16) = pf[3];
        *(uint4*)(base + 20480 + bn * 80 + bv * 16)  = pf[4];
        *(uint4*)(base + 25600 + bn * 80 + bv * 16)  = pf[5];
        *(uint4*)(base + 30720 + bn * 80 + bv * 16)  = pf[6];
        *(uint4*)(base + 35840 + bn * 80 + bv * 16)  = pf[7];
    };

    prefetch(0);
    for (int kc = 0; kc < KCH; kc++) {
        stage_store(hsm + (kc & 1) * STG);
        __syncthreads();
        if (kc + 1 < KCH) prefetch(kc + 1);   // LDGs in flight during MMA
        uint32_t sbase = sb + (kc & 1) * STG;

#pragma unroll
        for (int ks = 0; ks < 2; ks++) {
            uint32_t ahi[2][4], alo[2][4];
#pragma unroll
            for (int mt = 0; mt < 2; mt++) {
                uint32_t ad = sbase + (wm * 32 + mt * 16 + (lane & 15)) * 80
                            + ((lane >> 4) & 1) * 16 + ks * 32;
                ldm_x4(ahi[mt][0], ahi[mt][1], ahi[mt][2], ahi[mt][3], ad);
                ldm_x4(alo[mt][0], alo[mt][1], alo[mt][2], alo[mt][3], ad + 10240);
            }
#pragma unroll
            for (int hh = 0; hh < 2; hh++) {
                uint32_t bhi[4][2], blo[4][2];
                uint32_t bbase = sbase + 20480 + hh * 10240;
#pragma unroll
                for (int g2 = 0; g2 < 2; g2++) {
                    uint32_t bd = bbase
                        + (wn * 32 + g2 * 16 + (lane & 7) + ((lane >> 4) & 1) * 8) * 80
                        + ((lane >> 3) & 1) * 16 + ks * 32;
                    ldm_x4(bhi[2 * g2][0], bhi[2 * g2][1],
                           bhi[2 * g2 + 1][0], bhi[2 * g2 + 1][1], bd);
                    ldm_x4(blo[2 * g2][0], blo[2 * g2][1],
                           blo[2 * g2 + 1][0], blo[2 * g2 + 1][1], bd + 5120);
                }
#pragma unroll
                for (int mt = 0; mt < 2; mt++)
#pragma unroll
                    for (int nt = 0; nt < 4; nt++) {
                        mma_bf16(acc[hh][mt][nt], ahi[mt], bhi[nt][0], bhi[nt][1]);
                        mma_bf16(acc[hh][mt][nt], ahi[mt], blo[nt][0], blo[nt][1]);
                        mma_bf16(acc[hh][mt][nt], alo[mt], bhi[nt][0], bhi[nt][1]);
                    }
            }
        }
        __syncthreads();
    }

    // epilogue per head: relu(acc+bias) dot Wv -> per-row partials -> atomicAdd
    const float* bs[2] = { b00, b10 };
    const float* ws[2] = { W01, W11 };
    float* ys[2] = { y0, y1 };
#pragma unroll
    for (int hh = 0; hh < 2; hh++) {
        const float* bptr = bs[hh];
        const float* wv = ws[hh];
        float pr[2][2] = {{0.f, 0.f}, {0.f, 0.f}};
#pragma unroll
        for (int nt = 0; nt < 4; nt++) {
            int gc0 = col0 + wn * 32 + nt * 8 + 2 * (lane & 3);
            int gc1 = gc0 + 1;
            float bb0 = (gc0 < DDIM) ? bptr[gc0] : 0.f;
            float wv0 = (gc0 < DDIM) ? wv[gc0] : 0.f;
            float bb1 = (gc1 < DDIM) ? bptr[gc1] : 0.f;
            float wv1 = (gc1 < DDIM) ? wv[gc1] : 0.f;
#pragma unroll
            for (int mt = 0; mt < 2; mt++) {
                pr[mt][0] = fmaf(fmaxf(acc[hh][mt][nt][0] + bb0, 0.f), wv0, pr[mt][0]);
                pr[mt][0] = fmaf(fmaxf(acc[hh][mt][nt][1] + bb1, 0.f), wv1, pr[mt][0]);
                pr[mt][1] = fmaf(fmaxf(acc[hh][mt][nt][2] + bb0, 0.f), wv0, pr[mt][1]);
                pr[mt][1] = fmaf(fmaxf(acc[hh][mt][nt][3] + bb1, 0.f), wv1, pr[mt][1]);
            }
        }
#pragma unroll
        for (int off = 1; off <= 2; off <<= 1) {
#pragma unroll
            for (int mt = 0; mt < 2; mt++) {
                pr[mt][0] += __shfl_xor_sync(0xffffffffu, pr[mt][0], off);
                pr[mt][1] += __shfl_xor_sync(0xffffffffu, pr[mt][1], off);
            }
        }
        if ((lane & 3) == 0) {
            int rbase = row0 + wm * 32 + (lane >> 2);
#pragma unroll
            for (int mt = 0; mt < 2; mt++)
#pragma unroll
                for (int h2 = 0; h2 < 2; h2++) {
                    int grow = rbase + mt * 16 + h2 * 8;
                    if (grow < NN) atomicAdd(&ys[hh][grow], pr[mt][h2]);
                }
        }
    }
}

// ---------- launch ----------
extern "C" void kernel_launch(void* const* d_in, const int* in_sizes, int n_in,
                              void* d_out, int out_size)
{
    const float* X    = (const float*)d_in[0];
    const float* T    = (const float*)d_in[1];
    const int*   ei   = (const int*)d_in[2];
    const float* Wphi = (const float*)d_in[3];
    const float* bphi = (const float*)d_in[4];
    const float* Wgcn = (const float*)d_in[5];
    const float* bgcn = (const float*)d_in[6];
    const float* W00  = (const float*)d_in[7];
    const float* b00  = (const float*)d_in[8];
    const float* W10  = (const float*)d_in[9];
    const float* b10  = (const float*)d_in[10];
    const float* W01  = (const float*)d_in[11];
    const float* b01  = (const float*)d_in[12];
    const float* W11  = (const float*)d_in[13];
    const float* b11  = (const float*)d_in[14];

    float* out = (float*)d_out;
    float* y0  = out;
    float* y1  = out + NN;
    float* rep = out + 2 * NN;

    static cudaStream_t s2 = nullptr;
    static cudaEvent_t evF = nullptr, evJ = nullptr;
    if (!s2) {
        cudaStreamCreateWithFlags(&s2, cudaStreamNonBlocking);
        cudaEventCreateWithFlags(&evF, cudaEventDisableTiming);
        cudaEventCreateWithFlags(&evJ, cudaEventDisableTiming);
    }

    cudaFuncSetAttribute(k_phi, cudaFuncAttributeMaxDynamicSharedMemorySize, PHI_SMEM);
    cudaFuncSetAttribute(k_head_mma, cudaFuncAttributeMaxDynamicSharedMemorySize, HEAD_SMEM);

    // fork: edge/CSR chain on s2, GEMM work on default stream
    cudaEventRecord(evF, 0);
    cudaStreamWaitEvent(s2, evF, 0);

    k_zero<<<NB, 256, 0, s2>>>();
    k_edge1<<<(EE + 255) / 256, 256, 0, s2>>>(ei);
    k_blocksum<<<NB, 256, 0, s2>>>();
    k_scanblk<<<1, 512, 0, s2>>>();
    k_rowptr<<<NB, 256, 0, s2>>>(b01, b11, y0, y1);
    k_scatter<<<(EE + 255) / 256, 256, 0, s2>>>(ei);
    cudaEventRecord(evJ, s2);

    k_cvt_w<<<(2 * NPAD * KPAD + 255) / 256, 256>>>(W00, W10);
    k_phi<<<(NN + 127) / 128, 256, PHI_SMEM>>>(X, T, Wphi, bphi, Wgcn, rep);

    // join: gather needs CSR (s2) + g_h (default)
    cudaStreamWaitEvent(0, evJ, 0);
    k_gather<<<(NN * 32 + 255) / 256, 256>>>(T, bgcn, rep);
    dim3 gh((NN + 127) / 128, 5);
    k_head_mma<<<gh, 256, HEAD_SMEM>>>(b00, b10, W01, W11, y0, y1);
}

// round 11
// speedup vs baseline: 1.0572x; 1.0572x over previous
#include <cuda_runtime.h>
#include <cuda_bf16.h>
#include <cstdint>

#define NN 100000
#define EE 3200000
#define XDIM 256
#define HDIM 128
#define GDIM 128
#define DDIM 257
#define NB 391        // ceil(NN/256)
#define KPAD 288      // padded K for head GEMM (9 x 32)
#define NPAD 320      // padded N (5 x 64)
#define KCH 9

// ---------- scratch (device globals; no allocation allowed) ----------
__device__ float g_h[(size_t)NN * HDIM];
__device__ int   g_cnt[NN];
__device__ int   g_rowptr[NN + 1];
__device__ int   g_woff[NN];
__device__ int   g_csr[EE];
__device__ float g_dis[NN];
__device__ int   g_blksum[512];
__device__ __nv_bfloat16 g_rep_hi[(size_t)NN * KPAD];
__device__ __nv_bfloat16 g_rep_lo[(size_t)NN * KPAD];
__device__ __nv_bfloat16 g_wt[2][2][NPAD * KPAD];   // [head][hi/lo][n*KPAD+k]

// ---------- helpers ----------
__device__ __forceinline__ uint32_t smem_u32(const void* p) {
    uint32_t a;
    asm("{ .reg .u64 t; cvta.to.shared.u64 t, %1; cvt.u32.u64 %0, t; }"
        : "=r"(a) : "l"(p));
    return a;
}
__device__ __forceinline__ void ffma2(unsigned long long& d,
                                      unsigned long long a,
                                      unsigned long long b)
{
    asm("fma.rn.f32x2 %0, %1, %2, %3;" : "=l"(d) : "l"(a), "l"(b), "l"(d));
}
__device__ __forceinline__ void ldm_x4(uint32_t& r0, uint32_t& r1,
                                       uint32_t& r2, uint32_t& r3, uint32_t addr)
{
    asm volatile("ldmatrix.sync.aligned.m8n8.x4.shared.b16 {%0,%1,%2,%3}, [%4];"
        : "=r"(r0), "=r"(r1), "=r"(r2), "=r"(r3) : "r"(addr));
}
__device__ __forceinline__ void mma_bf16(float* c, const uint32_t* a,
                                         uint32_t b0, uint32_t b1)
{
    asm volatile("mma.sync.aligned.m16n8k16.row.col.f32.bf16.bf16.f32 "
        "{%0,%1,%2,%3}, {%4,%5,%6,%7}, {%8,%9}, {%0,%1,%2,%3};"
        : "+f"(c[0]), "+f"(c[1]), "+f"(c[2]), "+f"(c[3])
        : "r"(a[0]), "r"(a[1]), "r"(a[2]), "r"(a[3]), "r"(b0), "r"(b1));
}
__device__ __forceinline__ void bf16split(float x, __nv_bfloat16& hi, __nv_bfloat16& lo) {
    hi = __float2bfloat16(x);
    lo = __float2bfloat16(x - __bfloat162float(hi));
}

// ---------- kernel 0: zero degree counters ----------
__global__ void k_zero()
{
    int i = blockIdx.x * blockDim.x + threadIdx.x;
    if (i < NN) g_cnt[i] = 0;
}

// ---------- kernel 1: fused phi (FFMA2) + bf16 split of phi cols ----------
#define PHI_SMEM 83456
__global__ __launch_bounds__(256) void k_phi(
    const float* __restrict__ X, const float* __restrict__ T,
    const float* __restrict__ Wphi, const float* __restrict__ bphi,
    const float* __restrict__ Wgcn, float* __restrict__ out_rep)
{
    extern __shared__ float psm[];
    float* sXT = psm;             // [32][130]  phase1 A^T
    float* sW  = psm + 4160;      // [32][132]  phase1 W
    float* sPT = psm;             // [128][130] phase2 (T*phi)^T
    float* sWg = psm + 16640;     // [32][132]  phase2 W

    const int row0 = blockIdx.x * 128;
    const int t  = threadIdx.x;
    const int r0 = (t >> 5) * 16;
    const int c0 = (t & 31) * 4;

    unsigned long long acc2[8][4];
#pragma unroll
    for (int p = 0; p < 8; p++)
#pragma unroll
        for (int j = 0; j < 4; j++) acc2[p][j] = 0ull;

    // ---- phase 1: phi = X @ Wphi (K = 256) ----
    for (int k0 = 0; k0 < XDIM; k0 += 32) {
#pragma unroll
        for (int it = 0; it < 16; it++) {
            int q = t + it * 256;
            int r = q >> 5, kk = q & 31;
            int grow = row0 + r;
            sXT[kk * 130 + r] = (grow < NN) ? X[(size_t)grow * XDIM + k0 + kk] : 0.f;
        }
#pragma unroll
        for (int it = 0; it < 16; it++) {
            int q = t + it * 256;
            int kr = q >> 7, c = q & 127;
            sW[kr * 132 + c] = Wphi[(size_t)(k0 + kr) * HDIM + c];
        }
        __syncthreads();
#pragma unroll
        for (int kk = 0; kk < 32; kk++) {
            unsigned long long a2[8];
#pragma unroll
            for (int p = 0; p < 8; p++)
                a2[p] = *(const unsigned long long*)&sXT[kk * 130 + r0 + 2 * p];
            float4 w4 = *(const float4*)&sW[kk * 132 + c0];
            unsigned long long w2[4];
            asm("mov.b64 %0, {%1, %1};" : "=l"(w2[0]) : "f"(w4.x));
            asm("mov.b64 %0, {%1, %1};" : "=l"(w2[1]) : "f"(w4.y));
            asm("mov.b64 %0, {%1, %1};" : "=l"(w2[2]) : "f"(w4.z));
            asm("mov.b64 %0, {%1, %1};" : "=l"(w2[3]) : "f"(w4.w));
#pragma unroll
            for (int p = 0; p < 8; p++)
#pragma unroll
                for (int j = 0; j < 4; j++)
                    ffma2(acc2[p][j], a2[p], w2[j]);
        }
        __syncthreads();
    }

    // ---- epilogue 1: relu+bias -> rep (+bf16 split); T*phi -> sPT ----
#pragma unroll
    for (int p = 0; p < 8; p++) {
        int rA = r0 + 2 * p, rB = rA + 1;
        int gA = row0 + rA, gB = row0 + rB;
        float tA = (gA < NN) ? T[gA] : 0.f;
        float tB = (gB < NN) ? T[gB] : 0.f;
#pragma unroll
        for (int j = 0; j < 4; j++) {
            union { unsigned long long u; float2 f; } cv;
            cv.u = acc2[p][j];
            int c = c0 + j;
            float bb = bphi[c];
            float pA = fmaxf(cv.f.x + bb, 0.f);
            float pB = fmaxf(cv.f.y + bb, 0.f);
            __nv_bfloat16 hi, lo;
            if (gA < NN) {
                out_rep[(size_t)gA * DDIM + c] = pA;
                bf16split(pA, hi, lo);
                g_rep_hi[(size_t)gA * KPAD + c] = hi;
                g_rep_lo[(size_t)gA * KPAD + c] = lo;
            }
            if (gB < NN) {
                out_rep[(size_t)gB * DDIM + c] = pB;
                bf16split(pB, hi, lo);
                g_rep_hi[(size_t)gB * KPAD + c] = hi;
                g_rep_lo[(size_t)gB * KPAD + c] = lo;
            }
            sPT[c * 130 + rA] = pA * tA;
            sPT[c * 130 + rB] = pB * tB;
            acc2[p][j] = 0ull;
        }
    }
    __syncthreads();

    // ---- phase 2: h = (T*phi) @ Wgcn (K = 128) ----
    for (int k0 = 0; k0 < HDIM; k0 += 32) {
#pragma unroll
        for (int it = 0; it < 16; it++) {
            int q = t + it * 256;
            int kr = q >> 7, c = q & 127;
            sWg[kr * 132 + c] = Wgcn[(size_t)(k0 + kr) * GDIM + c];
        }
        __syncthreads();
#pragma unroll
        for (int kk = 0; kk < 32; kk++) {
            unsigned long long a2[8];
#pragma unroll
            for (int p = 0; p < 8; p++)
                a2[p] = *(const unsigned long long*)&sPT[(k0 + kk) * 130 + r0 + 2 * p];
            float4 w4 = *(const float4*)&sWg[kk * 132 + c0];
            unsigned long long w2[4];
            asm("mov.b64 %0, {%1, %1};" : "=l"(w2[0]) : "f"(w4.x));
            asm("mov.b64 %0, {%1, %1};" : "=l"(w2[1]) : "f"(w4.y));
            asm("mov.b64 %0, {%1, %1};" : "=l"(w2[2]) : "f"(w4.z));
            asm("mov.b64 %0, {%1, %1};" : "=l"(w2[3]) : "f"(w4.w));
#pragma unroll
            for (int p = 0; p < 8; p++)
#pragma unroll
                for (int j = 0; j < 4; j++)
                    ffma2(acc2[p][j], a2[p], w2[j]);
        }
        __syncthreads();
    }

#pragma unroll
    for (int p = 0; p < 8; p++) {
        int gA = row0 + r0 + 2 * p, gB = gA + 1;
#pragma unroll
        for (int j = 0; j < 4; j++) {
            union { unsigned long long u; float2 f; } cv;
            cv.u = acc2[p][j];
            int c = c0 + j;
            if (gA < NN) g_h[(size_t)gA * GDIM + c] = cv.f.x;
            if (gB < NN) g_h[(size_t)gB * GDIM + c] = cv.f.y;
        }
    }
}

// ---------- count in-degree ----------
__global__ void k_edge1(const int* __restrict__ ei)
{
    int e = blockIdx.x * blockDim.x + threadIdx.x;
    if (e >= EE) return;
    atomicAdd(&g_cnt[ei[EE + e]], 1);
}

// ---------- scan step 1 ----------
__global__ void k_blocksum()
{
    __shared__ int sm[8];
    int t = threadIdx.x;
    int i = blockIdx.x * 256 + t;
    int v = (i < NN) ? g_cnt[i] : 0;
#pragma unroll
    for (int off = 16; off >= 1; off >>= 1)
        v += __shfl_xor_sync(0xffffffffu, v, off);
    if ((t & 31) == 0) sm[t >> 5] = v;
    __syncthreads();
    if (t == 0) {
        int s = 0;
#pragma unroll
        for (int w = 0; w < 8; w++) s += sm[w];
        g_blksum[blockIdx.x] = s;
    }
}

// ---------- scan step 2 ----------
__global__ void k_scanblk()
{
    __shared__ int s[512];
    int t = threadIdx.x;
    int v = (t < NB) ? g_blksum[t] : 0;
    s[t] = v;
    __syncthreads();
    for (int off = 1; off < 512; off <<= 1) {
        int x = (t >= off) ? s[t - off] : 0;
        __syncthreads();
        s[t] += x;
        __syncthreads();
    }
    if (t < NB) g_blksum[t] = s[t] - v;
}

// ---------- scan step 3: rowptr + woff + dis + y bias init ----------
__global__ void k_rowptr(const float* __restrict__ b01, const float* __restrict__ b11,
                         float* __restrict__ y0, float* __restrict__ y1)
{
    __shared__ int s[256];
    int t = threadIdx.x;
    int i = blockIdx.x * 256 + t;
    int v = (i < NN) ? g_cnt[i] : 0;
    s[t] = v;
    __syncthreads();
    for (int off = 1; off < 256; off <<= 1) {
        int x = (t >= off) ? s[t - off] : 0;
        __syncthreads();
        s[t] += x;
        __syncthreads();
    }
    int incl = s[t];
    int base = g_blksum[blockIdx.x];
    if (i < NN) {
        int e = base + incl - v;
        g_rowptr[i] = e;
        g_woff[i]   = e;
        g_dis[i]    = rsqrtf((float)v + 1.0f);
        y0[i] = b01[0];
        y1[i] = b11[0];
    }
    if (i == NN - 1) g_rowptr[NN] = base + incl;
}

// ---------- scatter into CSR ----------
__global__ void k_scatter(const int* __restrict__ ei)
{
    int e = blockIdx.x * blockDim.x + threadIdx.x;
    if (e >= EE) return;
    int s = ei[e];
    int d = ei[EE + e];
    int pos = atomicAdd(&g_woff[d], 1);
    g_csr[pos] = s;
}

// ---------- warp-per-node gather: rep_gnn + z (+bf16 split cols 128..287) ----------
__global__ __launch_bounds__(256) void k_gather(
    const float* __restrict__ T, const float* __restrict__ bgcn,
    float* __restrict__ rep)
{
    int w = (blockIdx.x * 256 + threadIdx.x) >> 5;
    int lane = threadIdx.x & 31;
    if (w >= NN) return;
    int start = g_rowptr[w];
    int end   = g_rowptr[w + 1];
    float disd = g_dis[w];

    float4 acc = make_float4(0.f, 0.f, 0.f, 0.f);
    float zs = 0.f;
    int i = start;
    for (; i + 1 < end; i += 2) {
        int s0 = g_csr[i];
        int s1 = g_csr[i + 1];
        float cf0 = g_dis[s0] * disd;
        float cf1 = g_dis[s1] * disd;
        float4 h0 = *(const float4*)&g_h[(size_t)s0 * GDIM + lane * 4];
        float4 h1 = *(const float4*)&g_h[(size_t)s1 * GDIM + lane * 4];
        acc.x = fmaf(cf0, h0.x, acc.x); acc.x = fmaf(cf1, h1.x, acc.x);
        acc.y = fmaf(cf0, h0.y, acc.y); acc.y = fmaf(cf1, h1.y, acc.y);
        acc.z = fmaf(cf0, h0.z, acc.z); acc.z = fmaf(cf1, h1.z, acc.z);
        acc.w = fmaf(cf0, h0.w, acc.w); acc.w = fmaf(cf1, h1.w, acc.w);
        zs += T[s0] + T[s1];
    }
    if (i < end) {
        int s0 = g_csr[i];
        float cf0 = g_dis[s0] * disd;
        float4 h0 = *(const float4*)&g_h[(size_t)s0 * GDIM + lane * 4];
        acc.x = fmaf(cf0, h0.x, acc.x);
        acc.y = fmaf(cf0, h0.y, acc.y);
        acc.z = fmaf(cf0, h0.z, acc.z);
        acc.w = fmaf(cf0, h0.w, acc.w);
        zs += T[s0];
    }

    int cnt = end - start;
    float invd = 1.0f / ((float)cnt + 1.0f);
    float4 hd = *(const float4*)&g_h[(size_t)w * GDIM + lane * 4];
    int cb = lane * 4;
    float v0 = fmaxf(fmaf(hd.x, invd, acc.x) + bgcn[cb + 0], 0.f);
    float v1 = fmaxf(fmaf(hd.y, invd, acc.y) + bgcn[cb + 1], 0.f);
    float v2 = fmaxf(fmaf(hd.z, invd, acc.z) + bgcn[cb + 2], 0.f);
    float v3 = fmaxf(fmaf(hd.w, invd, acc.w) + bgcn[cb + 3], 0.f);
    float* o = &rep[(size_t)w * DDIM + 128 + cb];
    o[0] = v0; o[1] = v1; o[2] = v2; o[3] = v3;

    // bf16 split -> cols 128..255
    __nv_bfloat16 h4[4], l4[4];
    bf16split(v0, h4[0], l4[0]);
    bf16split(v1, h4[1], l4[1]);
    bf16split(v2, h4[2], l4[2]);
    bf16split(v3, h4[3], l4[3]);
    *(uint2*)&g_rep_hi[(size_t)w * KPAD + 128 + cb] = *(uint2*)h4;
    *(uint2*)&g_rep_lo[(size_t)w * KPAD + 128 + cb] = *(uint2*)l4;

    if (lane == 0) {
        float z = zs / fmaxf((float)cnt, 1.0f);
        rep[(size_t)w * DDIM + 256] = z;
        __nv_bfloat16 zh, zl;
        bf16split(z, zh, zl);
        g_rep_hi[(size_t)w * KPAD + 256] = zh;
        g_rep_lo[(size_t)w * KPAD + 256] = zl;
    } else {
        // zero pad cols 257..287
        g_rep_hi[(size_t)w * KPAD + 256 + lane] = __float2bfloat16(0.f);
        g_rep_lo[(size_t)w * KPAD + 256 + lane] = __float2bfloat16(0.f);
    }
}

// ---------- bf16 split of W00/W10 transposed ----------
__global__ void k_cvt_w(const float* __restrict__ W00, const float* __restrict__ W10)
{
    int idx = blockIdx.x * 256 + threadIdx.x;
    if (idx >= 2 * NPAD * KPAD) return;
    int head = idx / (NPAD * KPAD);
    int rem = idx - head * (NPAD * KPAD);
    int n = rem / KPAD, k = rem - n * KPAD;
    const float* W = head ? W10 : W00;
    float x = (n < DDIM && k < DDIM) ? W[(size_t)k * DDIM + n] : 0.f;
    __nv_bfloat16 hi, lo;
    bf16split(x, hi, lo);
    g_wt[head][0][rem] = hi;
    g_wt[head][1][rem] = lo;
}

// ---------- head GEMM: mma.sync bf16 3-pass, register-prefetch double-buffer ----
// CTA tile 128x64, warp tile 32x32, k-chunks of 32, 2-stage smem (80B pitch)
#define STG 30720
#define HEAD_SMEM (2 * STG)
__global__ __launch_bounds__(256, 2) void k_head_mma(
    const float* __restrict__ b00, const float* __restrict__ b10,
    const float* __restrict__ W01, const float* __restrict__ W11,
    float* __restrict__ y0, float* __restrict__ y1)
{
    extern __shared__ char hsm[];
    // per stage: A_hi @0 (10240B), A_lo @10240, B_hi @20480 (5120B), B_lo @25600
    uint32_t sb = smem_u32(hsm);
    const int tid = threadIdx.x, lane = tid & 31, wid = tid >> 5;
    const int wm = wid & 3, wn = wid >> 2;
    const int head = blockIdx.z;
    const int row0 = blockIdx.x * 128;
    const int col0 = blockIdx.y * 64;
    const float* bptr = head ? b10 : b00;
    const float* wv   = head ? W11 : W01;
    float* yo = head ? y1 : y0;
    const __nv_bfloat16* whi = g_wt[head][0];
    const __nv_bfloat16* wlo = g_wt[head][1];

    // per-thread load coordinates (fixed across chunks)
    const int ar0 = tid >> 2, av = tid & 3;       // A row / vec (it=0)
    const int ar1 = (tid + 256) >> 2;             // A row (it=1)
    const int bn = tid >> 2, bv = tid & 3;        // B n-row / vec
    const int okA0 = (row0 + ar0) < NN;
    const int okA1 = (row0 + ar1) < NN;
    const size_t gaoff0 = (size_t)(row0 + (okA0 ? ar0 : 0)) * KPAD + av * 8;
    const size_t gaoff1 = (size_t)(row0 + (okA1 ? ar1 : 0)) * KPAD + av * 8;
    const size_t gboff  = (size_t)(col0 + bn) * KPAD + bv * 8;

    float acc[2][4][4];
#pragma unroll
    for (int mt = 0; mt < 2; mt++)
#pragma unroll
        for (int nt = 0; nt < 4; nt++)
#pragma unroll
            for (int j = 0; j < 4; j++) acc[mt][nt][j] = 0.f;

    uint4 pf[6];
    auto prefetch = [&](int kc) {
        int kbase = kc * 32;
        pf[0] = okA0 ? *(const uint4*)&g_rep_hi[gaoff0 + kbase] : make_uint4(0,0,0,0);
        pf[1] = okA0 ? *(const uint4*)&g_rep_lo[gaoff0 + kbase] : make_uint4(0,0,0,0);
        pf[2] = okA1 ? *(const uint4*)&g_rep_hi[gaoff1 + kbase] : make_uint4(0,0,0,0);
        pf[3] = okA1 ? *(const uint4*)&g_rep_lo[gaoff1 + kbase] : make_uint4(0,0,0,0);
        pf[4] = *(const uint4*)&whi[gboff + kbase];
        pf[5] = *(const uint4*)&wlo[gboff + kbase];
    };
    auto stage_store = [&](char* base) {
        *(uint4*)(base + ar0 * 80 + av * 16)         = pf[0];
        *(uint4*)(base + 10240 + ar0 * 80 + av * 16) = pf[1];
        *(uint4*)(base + ar1 * 80 + av * 16)         = pf[2];
        *(uint4*)(base + 10240 + ar1 * 80 + av * 16) = pf[3];
        *(uint4*)(base + 20480 + bn * 80 + bv * 16)  = pf[4];
        *(uint4*)(base + 25600 + bn * 80 + bv * 16)  = pf[5];
    };

    prefetch(0);
    for (int kc = 0; kc < KCH; kc++) {
        stage_store(hsm + (kc & 1) * STG);
        __syncthreads();
        if (kc + 1 < KCH) prefetch(kc + 1);   // LDGs in flight during MMA
        uint32_t sbase = sb + (kc & 1) * STG;

#pragma unroll
        for (int ks = 0; ks < 2; ks++) {
            uint32_t ahi[2][4], alo[2][4], bhi[4][2], blo[4][2];
#pragma unroll
            for (int mt = 0; mt < 2; mt++) {
                uint32_t ad = sbase + (wm * 32 + mt * 16 + (lane & 15)) * 80
                            + ((lane >> 4) & 1) * 16 + ks * 32;
                ldm_x4(ahi[mt][0], ahi[mt][1], ahi[mt][2], ahi[mt][3], ad);
                ldm_x4(alo[mt][0], alo[mt][1], alo[mt][2], alo[mt][3], ad + 10240);
            }
#pragma unroll
            for (int g2 = 0; g2 < 2; g2++) {
                uint32_t bd = sbase + 20480
                            + (wn * 32 + g2 * 16 + (lane & 7) + ((lane >> 4) & 1) * 8) * 80
                            + ((lane >> 3) & 1) * 16 + ks * 32;
                ldm_x4(bhi[2 * g2][0], bhi[2 * g2][1], bhi[2 * g2 + 1][0], bhi[2 * g2 + 1][1], bd);
                ldm_x4(blo[2 * g2][0], blo[2 * g2][1], blo[2 * g2 + 1][0], blo[2 * g2 + 1][1], bd + 5120);
            }
#pragma unroll
            for (int mt = 0; mt < 2; mt++)
#pragma unroll
                for (int nt = 0; nt < 4; nt++) {
                    mma_bf16(acc[mt][nt], ahi[mt], bhi[nt][0], bhi[nt][1]);
                    mma_bf16(acc[mt][nt], ahi[mt], blo[nt][0], blo[nt][1]);
                    mma_bf16(acc[mt][nt], alo[mt], bhi[nt][0], bhi[nt][1]);
                }
        }
        __syncthreads();
    }

    // epilogue: relu(acc+bias) dot Wv -> per-row partials -> atomicAdd
    float pr[2][2] = {{0.f, 0.f}, {0.f, 0.f}};
#pragma unroll
    for (int nt = 0; nt < 4; nt++) {
        int gc0 = col0 + wn * 32 + nt * 8 + 2 * (lane & 3);
        int gc1 = gc0 + 1;
        float bb0 = (gc0 < DDIM) ? bptr[gc0] : 0.f;
        float wv0 = (gc0 < DDIM) ? wv[gc0] : 0.f;
        float bb1 = (gc1 < DDIM) ? bptr[gc1] : 0.f;
        float wv1 = (gc1 < DDIM) ? wv[gc1] : 0.f;
#pragma unroll
        for (int mt = 0; mt < 2; mt++) {
            pr[mt][0] = fmaf(fmaxf(acc[mt][nt][0] + bb0, 0.f), wv0, pr[mt][0]);
            pr[mt][0] = fmaf(fmaxf(acc[mt][nt][1] + bb1, 0.f), wv1, pr[mt][0]);
            pr[mt][1] = fmaf(fmaxf(acc[mt][nt][2] + bb0, 0.f), wv0, pr[mt][1]);
            pr[mt][1] = fmaf(fmaxf(acc[mt][nt][3] + bb1, 0.f), wv1, pr[mt][1]);
        }
    }
#pragma unroll
    for (int off = 1; off <= 2; off <<= 1) {
#pragma unroll
        for (int mt = 0; mt < 2; mt++) {
            pr[mt][0] += __shfl_xor_sync(0xffffffffu, pr[mt][0], off);
            pr[mt][1] += __shfl_xor_sync(0xffffffffu, pr[mt][1], off);
        }
    }
    if ((lane & 3) == 0) {
        int rbase = row0 + wm * 32 + (lane >> 2);
#pragma unroll
        for (int mt = 0; mt < 2; mt++)
#pragma unroll
            for (int h = 0; h < 2; h++) {
                int grow = rbase + mt * 16 + h * 8;
                if (grow < NN) atomicAdd(&yo[grow], pr[mt][h]);
            }
    }
}

// ---------- launch ----------
extern "C" void kernel_launch(void* const* d_in, const int* in_sizes, int n_in,
                              void* d_out, int out_size)
{
    const float* X    = (const float*)d_in[0];
    const float* T    = (const float*)d_in[1];
    const int*   ei   = (const int*)d_in[2];
    const float* Wphi = (const float*)d_in[3];
    const float* bphi = (const float*)d_in[4];
    const float* Wgcn = (const float*)d_in[5];
    const float* bgcn = (const float*)d_in[6];
    const float* W00  = (const float*)d_in[7];
    const float* b00  = (const float*)d_in[8];
    const float* W10  = (const float*)d_in[9];
    const float* b10  = (const float*)d_in[10];
    const float* W01  = (const float*)d_in[11];
    const float* b01  = (const float*)d_in[12];
    const float* W11  = (const float*)d_in[13];
    const float* b11  = (const float*)d_in[14];

    float* out = (float*)d_out;
    float* y0  = out;
    float* y1  = out + NN;
    float* rep = out + 2 * NN;

    static cudaStream_t s2 = nullptr;
    static cudaEvent_t evF = nullptr, evJ = nullptr;
    if (!s2) {
        cudaStreamCreateWithFlags(&s2, cudaStreamNonBlocking);
        cudaEventCreateWithFlags(&evF, cudaEventDisableTiming);
        cudaEventCreateWithFlags(&evJ, cudaEventDisableTiming);
    }

    cudaFuncSetAttribute(k_phi, cudaFuncAttributeMaxDynamicSharedMemorySize, PHI_SMEM);
    cudaFuncSetAttribute(k_head_mma, cudaFuncAttributeMaxDynamicSharedMemorySize, HEAD_SMEM);

    // fork: weight-convert + edge/CSR chain on s2, GEMM work on default stream
    cudaEventRecord(evF, 0);
    cudaStreamWaitEvent(s2, evF, 0);

    k_cvt_w<<<(2 * NPAD * KPAD + 255) / 256, 256, 0, s2>>>(W00, W10);
    k_zero<<<NB, 256, 0, s2>>>();
    k_edge1<<<(EE + 255) / 256, 256, 0, s2>>>(ei);
    k_blocksum<<<NB, 256, 0, s2>>>();
    k_scanblk<<<1, 512, 0, s2>>>();
    k_rowptr<<<NB, 256, 0, s2>>>(b01, b11, y0, y1);
    k_scatter<<<(EE + 255) / 256, 256, 0, s2>>>(ei);
    cudaEventRecord(evJ, s2);

    k_phi<<<(NN + 127) / 128, 256, PHI_SMEM>>>(X, T, Wphi, bphi, Wgcn, rep);

    // join: gather needs CSR (s2) + g_h (default); head needs cvt_w + y init
    cudaStreamWaitEvent(0, evJ, 0);
    k_gather<<<(NN * 32 + 255) / 256, 256>>>(T, bgcn, rep);
    dim3 gh((NN + 127) / 128, 5, 2);
    k_head_mma<<<gh, 256, HEAD_SMEM>>>(b00, b10, W01, W11, y0, y1);
}

// round 12
// speedup vs baseline: 1.2178x; 1.1519x over previous
#include <cuda_runtime.h>
#include <cuda_bf16.h>
#include <cstdint>

#define NN 100000
#define EE 3200000
#define XDIM 256
#define HDIM 128
#define GDIM 128
#define DDIM 257
#define NB 391        // ceil(NN/256)
#define KPAD 288      // padded K for head GEMM (9 x 32)
#define NPAD 320      // padded N (5 x 64)
#define KCH 9

// ---------- scratch (device globals; no allocation allowed) ----------
__device__ float g_h[(size_t)NN * HDIM];
__device__ int   g_cnt[NN];
__device__ int   g_rowptr[NN + 1];
__device__ int   g_woff[NN];
__device__ int   g_csr[EE];
__device__ float g_dis[NN];
__device__ int   g_blksum[512];
__device__ __nv_bfloat16 g_rep_hi[(size_t)NN * KPAD];
__device__ __nv_bfloat16 g_rep_lo[(size_t)NN * KPAD];
__device__ __nv_bfloat16 g_wt[2][2][NPAD * KPAD];    // head W^T [head][hi/lo][n*KPAD+k]
__device__ __nv_bfloat16 g_wphit[2][HDIM * XDIM];    // Wphi^T [hi/lo][n*256+k]
__device__ __nv_bfloat16 g_wgcnt[2][GDIM * HDIM];    // Wgcn^T [hi/lo][n*128+k]

// ---------- helpers ----------
__device__ __forceinline__ uint32_t smem_u32(const void* p) {
    uint32_t a;
    asm("{ .reg .u64 t; cvta.to.shared.u64 t, %1; cvt.u32.u64 %0, t; }"
        : "=r"(a) : "l"(p));
    return a;
}
__device__ __forceinline__ void ldm_x4(uint32_t& r0, uint32_t& r1,
                                       uint32_t& r2, uint32_t& r3, uint32_t addr)
{
    asm volatile("ldmatrix.sync.aligned.m8n8.x4.shared.b16 {%0,%1,%2,%3}, [%4];"
        : "=r"(r0), "=r"(r1), "=r"(r2), "=r"(r3) : "r"(addr));
}
__device__ __forceinline__ void mma_bf16(float* c, const uint32_t* a,
                                         uint32_t b0, uint32_t b1)
{
    asm volatile("mma.sync.aligned.m16n8k16.row.col.f32.bf16.bf16.f32 "
        "{%0,%1,%2,%3}, {%4,%5,%6,%7}, {%8,%9}, {%0,%1,%2,%3};"
        : "+f"(c[0]), "+f"(c[1]), "+f"(c[2]), "+f"(c[3])
        : "r"(a[0]), "r"(a[1]), "r"(a[2]), "r"(a[3]), "r"(b0), "r"(b1));
}
__device__ __forceinline__ void bf16split(float x, __nv_bfloat16& hi, __nv_bfloat16& lo) {
    hi = __float2bfloat16(x);
    lo = __float2bfloat16(x - __bfloat162float(hi));
}

// ---------- kernel 0: zero degree counters ----------
__global__ void k_zero()
{
    int i = blockIdx.x * blockDim.x + threadIdx.x;
    if (i < NN) g_cnt[i] = 0;
}

// ---------- transpose+split phi/gcn weights ----------
__global__ void k_cvt_w2(const float* __restrict__ Wphi, const float* __restrict__ Wgcn)
{
    int idx = blockIdx.x * 256 + threadIdx.x;
    if (idx < HDIM * XDIM) {
        int n = idx >> 8, k = idx & 255;
        __nv_bfloat16 hi, lo;
        bf16split(Wphi[(size_t)k * HDIM + n], hi, lo);
        g_wphit[0][idx] = hi;
        g_wphit[1][idx] = lo;
    } else if (idx < HDIM * XDIM + GDIM * HDIM) {
        int r = idx - HDIM * XDIM;
        int n = r >> 7, k = r & 127;
        __nv_bfloat16 hi, lo;
        bf16split(Wgcn[(size_t)k * GDIM + n], hi, lo);
        g_wgcnt[0][r] = hi;
        g_wgcnt[1][r] = lo;
    }
}

// ---------- phi via mma.sync bf16 3-pass ----------
// CTA 64 rows x 128 cols; 8 warps, warp tile 32x32 (wm 0-1, wn 0-3)
// smem: A2_hi 0..20480, A2_lo 20480..40960,
//       stages @40960 + s*30720: {A1_hi 5120, A1_lo 5120, B_hi 10240, B_lo 10240}
#define PHI2_SMEM 102400
__global__ __launch_bounds__(256, 2) void k_phi_mma(
    const float* __restrict__ X, const float* __restrict__ T,
    const float* __restrict__ bphi, float* __restrict__ out_rep)
{
    extern __shared__ char psm[];
    uint32_t sb = smem_u32(psm);
    const int tid = threadIdx.x, lane = tid & 31, wid = tid >> 5;
    const int wm = wid & 1, wn = wid >> 1;
    const int row0 = blockIdx.x * 64;

    const int ar = tid >> 2, av = tid & 3;       // A loader: row / 8-float vec
    const int okA = (row0 + ar) < NN;
    const float* xsrc = X + (size_t)(row0 + (okA ? ar : 0)) * XDIM + av * 8;

    float acc[2][4][4];
#pragma unroll
    for (int mt = 0; mt < 2; mt++)
#pragma unroll
        for (int nt = 0; nt < 4; nt++)
#pragma unroll
            for (int j = 0; j < 4; j++) acc[mt][nt][j] = 0.f;

    float4 pxa, pxb;
    uint4 pb[4];
    auto pre1 = [&](int kc) {
        int kb = kc * 32;
        pxa = okA ? *(const float4*)(xsrc + kb)     : make_float4(0, 0, 0, 0);
        pxb = okA ? *(const float4*)(xsrc + kb + 4) : make_float4(0, 0, 0, 0);
#pragma unroll
        for (int it = 0; it < 2; it++) {
            int q = tid + it * 256;
            int n = q >> 2, v = q & 3;
            pb[2 * it]     = *(const uint4*)&g_wphit[0][n * XDIM + kb + v * 8];
            pb[2 * it + 1] = *(const uint4*)&g_wphit[1][n * XDIM + kb + v * 8];
        }
    };
    auto st1 = [&](char* base) {
        float f[8] = { pxa.x, pxa.y, pxa.z, pxa.w, pxb.x, pxb.y, pxb.z, pxb.w };
        __nv_bfloat16 hb[8], lb[8];
#pragma unroll
        for (int i = 0; i < 8; i++) bf16split(f[i], hb[i], lb[i]);
        *(uint4*)(base + ar * 80 + av * 16)        = *(uint4*)hb;
        *(uint4*)(base + 5120 + ar * 80 + av * 16) = *(uint4*)lb;
#pragma unroll
        for (int it = 0; it < 2; it++) {
            int q = tid + it * 256;
            int n = q >> 2, v = q & 3;
            *(uint4*)(base + 10240 + n * 80 + v * 16) = pb[2 * it];
            *(uint4*)(base + 20480 + n * 80 + v * 16) = pb[2 * it + 1];
        }
    };

    // ---- phase 1: phi = X @ Wphi (8 k-chunks) ----
    pre1(0);
    for (int kc = 0; kc < 8; kc++) {
        st1(psm + 40960 + (kc & 1) * 30720);
        __syncthreads();
        if (kc + 1 < 8) pre1(kc + 1);
        uint32_t aB = sb + 40960 + (kc & 1) * 30720;
        uint32_t bB = aB + 10240;
#pragma unroll
        for (int ks = 0; ks < 2; ks++) {
            uint32_t ahi[2][4], alo[2][4], bhi[4][2], blo[4][2];
#pragma unroll
            for (int mt = 0; mt < 2; mt++) {
                uint32_t ad = aB + (wm * 32 + mt * 16 + (lane & 15)) * 80
                            + ((lane >> 4) & 1) * 16 + ks * 32;
                ldm_x4(ahi[mt][0], ahi[mt][1], ahi[mt][2], ahi[mt][3], ad);
                ldm_x4(alo[mt][0], alo[mt][1], alo[mt][2], alo[mt][3], ad + 5120);
            }
#pragma unroll
            for (int g2 = 0; g2 < 2; g2++) {
                uint32_t bd = bB + (wn * 32 + g2 * 16 + (lane & 7) + ((lane >> 4) & 1) * 8) * 80
                            + ((lane >> 3) & 1) * 16 + ks * 32;
                ldm_x4(bhi[2 * g2][0], bhi[2 * g2][1], bhi[2 * g2 + 1][0], bhi[2 * g2 + 1][1], bd);
                ldm_x4(blo[2 * g2][0], blo[2 * g2][1], blo[2 * g2 + 1][0], blo[2 * g2 + 1][1], bd + 10240);
            }
#pragma unroll
            for (int mt = 0; mt < 2; mt++)
#pragma unroll
                for (int nt = 0; nt < 4; nt++) {
                    mma_bf16(acc[mt][nt], ahi[mt], bhi[nt][0], bhi[nt][1]);
                    mma_bf16(acc[mt][nt], ahi[mt], blo[nt][0], blo[nt][1]);
                    mma_bf16(acc[mt][nt], alo[mt], bhi[nt][0], bhi[nt][1]);
                }
        }
        __syncthreads();
    }

    // ---- epilogue 1: relu+bias -> rep (+bf16 split); (T*phi) hi/lo -> A2 smem ----
#pragma unroll
    for (int mt = 0; mt < 2; mt++)
#pragma unroll
        for (int j2 = 0; j2 < 2; j2++) {
            int r = wm * 32 + mt * 16 + (lane >> 2) + 8 * j2;
            int g = row0 + r;
            float tv = (g < NN) ? T[g] : 0.f;
#pragma unroll
            for (int nt = 0; nt < 4; nt++)
#pragma unroll
                for (int jj = 0; jj < 2; jj++) {
                    int j = j2 * 2 + jj;
                    int c = wn * 32 + nt * 8 + 2 * (lane & 3) + jj;
                    float p = fmaxf(acc[mt][nt][j] + bphi[c], 0.f);
                    if (g < NN) {
                        out_rep[(size_t)g * DDIM + c] = p;
                        __nv_bfloat16 hi, lo;
                        bf16split(p, hi, lo);
                        g_rep_hi[(size_t)g * KPAD + c] = hi;
                        g_rep_lo[(size_t)g * KPAD + c] = lo;
                    }
                    float tp = p * tv;
                    __nv_bfloat16 th, tl;
                    bf16split(tp, th, tl);
                    uint32_t off = (c >> 5) * 5120 + r * 80 + ((c & 31) >> 3) * 16 + (c & 7) * 2;
                    *(__nv_bfloat16*)(psm + off) = th;
                    *(__nv_bfloat16*)(psm + 20480 + off) = tl;
                    acc[mt][nt][j] = 0.f;
                }
        }
    __syncthreads();

    // ---- phase 2: h = (T*phi) @ Wgcn (4 k-chunks, A from A2 smem) ----
    auto pre2 = [&](int kc) {
        int kb = kc * 32;
#pragma unroll
        for (int it = 0; it < 2; it++) {
            int q = tid + it * 256;
            int n = q >> 2, v = q & 3;
            pb[2 * it]     = *(const uint4*)&g_wgcnt[0][n * HDIM + kb + v * 8];
            pb[2 * it + 1] = *(const uint4*)&g_wgcnt[1][n * HDIM + kb + v * 8];
        }
    };
    auto st2 = [&](char* base) {
#pragma unroll
        for (int it = 0; it < 2; it++) {
            int q = tid + it * 256;
            int n = q >> 2, v = q & 3;
            *(uint4*)(base + 10240 + n * 80 + v * 16) = pb[2 * it];
            *(uint4*)(base + 20480 + n * 80 + v * 16) = pb[2 * it + 1];
        }
    };
    pre2(0);
    for (int kc = 0; kc < 4; kc++) {
        st2(psm + 40960 + (kc & 1) * 30720);
        __syncthreads();
        if (kc + 1 < 4) pre2(kc + 1);
        uint32_t aB = sb + kc * 5120;
        uint32_t bB = sb + 40960 + (kc & 1) * 30720 + 10240;
#pragma unroll
        for (int ks = 0; ks < 2; ks++) {
            uint32_t ahi[2][4], alo[2][4], bhi[4][2], blo[4][2];
#pragma unroll
            for (int mt = 0; mt < 2; mt++) {
                uint32_t ad = aB + (wm * 32 + mt * 16 + (lane & 15)) * 80
                            + ((lane >> 4) & 1) * 16 + ks * 32;
                ldm_x4(ahi[mt][0], ahi[mt][1], ahi[mt][2], ahi[mt][3], ad);
                ldm_x4(alo[mt][0], alo[mt][1], alo[mt][2], alo[mt][3], ad + 20480);
            }
#pragma unroll
            for (int g2 = 0; g2 < 2; g2++) {
                uint32_t bd = bB + (wn * 32 + g2 * 16 + (lane & 7) + ((lane >> 4) & 1) * 8) * 80
                            + ((lane >> 3) & 1) * 16 + ks * 32;
                ldm_x4(bhi[2 * g2][0], bhi[2 * g2][1], bhi[2 * g2 + 1][0], bhi[2 * g2 + 1][1], bd);
                ldm_x4(blo[2 * g2][0], blo[2 * g2][1], blo[2 * g2 + 1][0], blo[2 * g2 + 1][1], bd + 10240);
            }
#pragma unroll
            for (int mt = 0; mt < 2; mt++)
#pragma unroll
                for (int nt = 0; nt < 4; nt++) {
                    mma_bf16(acc[mt][nt], ahi[mt], bhi[nt][0], bhi[nt][1]);
                    mma_bf16(acc[mt][nt], ahi[mt], blo[nt][0], blo[nt][1]);
                    mma_bf16(acc[mt][nt], alo[mt], bhi[nt][0], bhi[nt][1]);
                }
        }
        __syncthreads();
    }

    // ---- epilogue 2: h -> g_h ----
#pragma unroll
    for (int mt = 0; mt < 2; mt++)
#pragma unroll
        for (int j2 = 0; j2 < 2; j2++) {
            int r = wm * 32 + mt * 16 + (lane >> 2) + 8 * j2;
            int g = row0 + r;
            if (g < NN) {
#pragma unroll
                for (int nt = 0; nt < 4; nt++)
#pragma unroll
                    for (int jj = 0; jj < 2; jj++) {
                        int c = wn * 32 + nt * 8 + 2 * (lane & 3) + jj;
                        g_h[(size_t)g * GDIM + c] = acc[mt][nt][j2 * 2 + jj];
                    }
            }
        }
}

// ---------- count in-degree ----------
__global__ void k_edge1(const int* __restrict__ ei)
{
    int e = blockIdx.x * blockDim.x + threadIdx.x;
    if (e >= EE) return;
    atomicAdd(&g_cnt[ei[EE + e]], 1);
}

// ---------- scan step 1 ----------
__global__ void k_blocksum()
{
    __shared__ int sm[8];
    int t = threadIdx.x;
    int i = blockIdx.x * 256 + t;
    int v = (i < NN) ? g_cnt[i] : 0;
#pragma unroll
    for (int off = 16; off >= 1; off >>= 1)
        v += __shfl_xor_sync(0xffffffffu, v, off);
    if ((t & 31) == 0) sm[t >> 5] = v;
    __syncthreads();
    if (t == 0) {
        int s = 0;
#pragma unroll
        for (int w = 0; w < 8; w++) s += sm[w];
        g_blksum[blockIdx.x] = s;
    }
}

// ---------- scan step 2 ----------
__global__ void k_scanblk()
{
    __shared__ int s[512];
    int t = threadIdx.x;
    int v = (t < NB) ? g_blksum[t] : 0;
    s[t] = v;
    __syncthreads();
    for (int off = 1; off < 512; off <<= 1) {
        int x = (t >= off) ? s[t - off] : 0;
        __syncthreads();
        s[t] += x;
        __syncthreads();
    }
    if (t < NB) g_blksum[t] = s[t] - v;
}

// ---------- scan step 3: rowptr + woff + dis + y bias init ----------
__global__ void k_rowptr(const float* __restrict__ b01, const float* __restrict__ b11,
                         float* __restrict__ y0, float* __restrict__ y1)
{
    __shared__ int s[256];
    int t = threadIdx.x;
    int i = blockIdx.x * 256 + t;
    int v = (i < NN) ? g_cnt[i] : 0;
    s[t] = v;
    __syncthreads();
    for (int off = 1; off < 256; off <<= 1) {
        int x = (t >= off) ? s[t - off] : 0;
        __syncthreads();
        s[t] += x;
        __syncthreads();
    }
    int incl = s[t];
    int base = g_blksum[blockIdx.x];
    if (i < NN) {
        int e = base + incl - v;
        g_rowptr[i] = e;
        g_woff[i]   = e;
        g_dis[i]    = rsqrtf((float)v + 1.0f);
        y0[i] = b01[0];
        y1[i] = b11[0];
    }
    if (i == NN - 1) g_rowptr[NN] = base + incl;
}

// ---------- scatter into CSR ----------
__global__ void k_scatter(const int* __restrict__ ei)
{
    int e = blockIdx.x * blockDim.x + threadIdx.x;
    if (e >= EE) return;
    int s = ei[e];
    int d = ei[EE + e];
    int pos = atomicAdd(&g_woff[d], 1);
    g_csr[pos] = s;
}

// ---------- warp-per-node gather: rep_gnn + z (+bf16 split cols 128..287) ----------
__global__ __launch_bounds__(256) void k_gather(
    const float* __restrict__ T, const float* __restrict__ bgcn,
    float* __restrict__ rep)
{
    int w = (blockIdx.x * 256 + threadIdx.x) >> 5;
    int lane = threadIdx.x & 31;
    if (w >= NN) return;
    int start = g_rowptr[w];
    int end   = g_rowptr[w + 1];
    float disd = g_dis[w];

    float4 acc = make_float4(0.f, 0.f, 0.f, 0.f);
    float zs = 0.f;
    int i = start;
    for (; i + 1 < end; i += 2) {
        int s0 = g_csr[i];
        int s1 = g_csr[i + 1];
        float cf0 = g_dis[s0] * disd;
        float cf1 = g_dis[s1] * disd;
        float4 h0 = *(const float4*)&g_h[(size_t)s0 * GDIM + lane * 4];
        float4 h1 = *(const float4*)&g_h[(size_t)s1 * GDIM + lane * 4];
        acc.x = fmaf(cf0, h0.x, acc.x); acc.x = fmaf(cf1, h1.x, acc.x);
        acc.y = fmaf(cf0, h0.y, acc.y); acc.y = fmaf(cf1, h1.y, acc.y);
        acc.z = fmaf(cf0, h0.z, acc.z); acc.z = fmaf(cf1, h1.z, acc.z);
        acc.w = fmaf(cf0, h0.w, acc.w); acc.w = fmaf(cf1, h1.w, acc.w);
        zs += T[s0] + T[s1];
    }
    if (i < end) {
        int s0 = g_csr[i];
        float cf0 = g_dis[s0] * disd;
        float4 h0 = *(const float4*)&g_h[(size_t)s0 * GDIM + lane * 4];
        acc.x = fmaf(cf0, h0.x, acc.x);
        acc.y = fmaf(cf0, h0.y, acc.y);
        acc.z = fmaf(cf0, h0.z, acc.z);
        acc.w = fmaf(cf0, h0.w, acc.w);
        zs += T[s0];
    }

    int cnt = end - start;
    float invd = 1.0f / ((float)cnt + 1.0f);
    float4 hd = *(const float4*)&g_h[(size_t)w * GDIM + lane * 4];
    int cb = lane * 4;
    float v0 = fmaxf(fmaf(hd.x, invd, acc.x) + bgcn[cb + 0], 0.f);
    float v1 = fmaxf(fmaf(hd.y, invd, acc.y) + bgcn[cb + 1], 0.f);
    float v2 = fmaxf(fmaf(hd.z, invd, acc.z) + bgcn[cb + 2], 0.f);
    float v3 = fmaxf(fmaf(hd.w, invd, acc.w) + bgcn[cb + 3], 0.f);
    float* o = &rep[(size_t)w * DDIM + 128 + cb];
    o[0] = v0; o[1] = v1; o[2] = v2; o[3] = v3;

    __nv_bfloat16 h4[4], l4[4];
    bf16split(v0, h4[0], l4[0]);
    bf16split(v1, h4[1], l4[1]);
    bf16split(v2, h4[2], l4[2]);
    bf16split(v3, h4[3], l4[3]);
    *(uint2*)&g_rep_hi[(size_t)w * KPAD + 128 + cb] = *(uint2*)h4;
    *(uint2*)&g_rep_lo[(size_t)w * KPAD + 128 + cb] = *(uint2*)l4;

    if (lane == 0) {
        float z = zs / fmaxf((float)cnt, 1.0f);
        rep[(size_t)w * DDIM + 256] = z;
        __nv_bfloat16 zh, zl;
        bf16split(z, zh, zl);
        g_rep_hi[(size_t)w * KPAD + 256] = zh;
        g_rep_lo[(size_t)w * KPAD + 256] = zl;
    } else {
        g_rep_hi[(size_t)w * KPAD + 256 + lane] = __float2bfloat16(0.f);
        g_rep_lo[(size_t)w * KPAD + 256 + lane] = __float2bfloat16(0.f);
    }
}

// ---------- bf16 split of W00/W10 transposed ----------
__global__ void k_cvt_w(const float* __restrict__ W00, const float* __restrict__ W10)
{
    int idx = blockIdx.x * 256 + threadIdx.x;
    if (idx >= 2 * NPAD * KPAD) return;
    int head = idx / (NPAD * KPAD);
    int rem = idx - head * (NPAD * KPAD);
    int n = rem / KPAD, k = rem - n * KPAD;
    const float* W = head ? W10 : W00;
    float x = (n < DDIM && k < DDIM) ? W[(size_t)k * DDIM + n] : 0.f;
    __nv_bfloat16 hi, lo;
    bf16split(x, hi, lo);
    g_wt[head][0][rem] = hi;
    g_wt[head][1][rem] = lo;
}

// ---------- head GEMM: mma.sync bf16 3-pass, register-prefetch double-buffer ----
#define STG 30720
#define HEAD_SMEM (2 * STG)
__global__ __launch_bounds__(256, 2) void k_head_mma(
    const float* __restrict__ b00, const float* __restrict__ b10,
    const float* __restrict__ W01, const float* __restrict__ W11,
    float* __restrict__ y0, float* __restrict__ y1)
{
    extern __shared__ char hsm[];
    uint32_t sb = smem_u32(hsm);
    const int tid = threadIdx.x, lane = tid & 31, wid = tid >> 5;
    const int wm = wid & 3, wn = wid >> 2;
    const int head = blockIdx.z;
    const int row0 = blockIdx.x * 128;
    const int col0 = blockIdx.y * 64;
    const float* bptr = head ? b10 : b00;
    const float* wv   = head ? W11 : W01;
    float* yo = head ? y1 : y0;
    const __nv_bfloat16* whi = g_wt[head][0];
    const __nv_bfloat16* wlo = g_wt[head][1];

    const int ar0 = tid >> 2, av = tid & 3;
    const int ar1 = (tid + 256) >> 2;
    const int bn = tid >> 2, bv = tid & 3;
    const int okA0 = (row0 + ar0) < NN;
    const int okA1 = (row0 + ar1) < NN;
    const size_t gaoff0 = (size_t)(row0 + (okA0 ? ar0 : 0)) * KPAD + av * 8;
    const size_t gaoff1 = (size_t)(row0 + (okA1 ? ar1 : 0)) * KPAD + av * 8;
    const size_t gboff  = (size_t)(col0 + bn) * KPAD + bv * 8;

    float acc[2][4][4];
#pragma unroll
    for (int mt = 0; mt < 2; mt++)
#pragma unroll
        for (int nt = 0; nt < 4; nt++)
#pragma unroll
            for (int j = 0; j < 4; j++) acc[mt][nt][j] = 0.f;

    uint4 pf[6];
    auto prefetch = [&](int kc) {
        int kbase = kc * 32;
        pf[0] = okA0 ? *(const uint4*)&g_rep_hi[gaoff0 + kbase] : make_uint4(0,0,0,0);
        pf[1] = okA0 ? *(const uint4*)&g_rep_lo[gaoff0 + kbase] : make_uint4(0,0,0,0);
        pf[2] = okA1 ? *(const uint4*)&g_rep_hi[gaoff1 + kbase] : make_uint4(0,0,0,0);
        pf[3] = okA1 ? *(const uint4*)&g_rep_lo[gaoff1 + kbase] : make_uint4(0,0,0,0);
        pf[4] = *(const uint4*)&whi[gboff + kbase];
        pf[5] = *(const uint4*)&wlo[gboff + kbase];
    };
    auto stage_store = [&](char* base) {
        *(uint4*)(base + ar0 * 80 + av * 16)         = pf[0];
        *(uint4*)(base + 10240 + ar0 * 80 + av * 16) = pf[1];
        *(uint4*)(base + ar1 * 80 + av * 16)         = pf[2];
        *(uint4*)(base + 10240 + ar1 * 80 + av * 16) = pf[3];
        *(uint4*)(base + 20480 + bn * 80 + bv * 16)  = pf[4];
        *(uint4*)(base + 25600 + bn * 80 + bv * 16)  = pf[5];
    };

    prefetch(0);
    for (int kc = 0; kc < KCH; kc++) {
        stage_store(hsm + (kc & 1) * STG);
        __syncthreads();
        if (kc + 1 < KCH) prefetch(kc + 1);
        uint32_t sbase = sb + (kc & 1) * STG;

#pragma unroll
        for (int ks = 0; ks < 2; ks++) {
            uint32_t ahi[2][4], alo[2][4], bhi[4][2], blo[4][2];
#pragma unroll
            for (int mt = 0; mt < 2; mt++) {
                uint32_t ad = sbase + (wm * 32 + mt * 16 + (lane & 15)) * 80
                            + ((lane >> 4) & 1) * 16 + ks * 32;
                ldm_x4(ahi[mt][0], ahi[mt][1], ahi[mt][2], ahi[mt][3], ad);
                ldm_x4(alo[mt][0], alo[mt][1], alo[mt][2], alo[mt][3], ad + 10240);
            }
#pragma unroll
            for (int g2 = 0; g2 < 2; g2++) {
                uint32_t bd = sbase + 20480
                            + (wn * 32 + g2 * 16 + (lane & 7) + ((lane >> 4) & 1) * 8) * 80
                            + ((lane >> 3) & 1) * 16 + ks * 32;
                ldm_x4(bhi[2 * g2][0], bhi[2 * g2][1], bhi[2 * g2 + 1][0], bhi[2 * g2 + 1][1], bd);
                ldm_x4(blo[2 * g2][0], blo[2 * g2][1], blo[2 * g2 + 1][0], blo[2 * g2 + 1][1], bd + 5120);
            }
#pragma unroll
            for (int mt = 0; mt < 2; mt++)
#pragma unroll
                for (int nt = 0; nt < 4; nt++) {
                    mma_bf16(acc[mt][nt], ahi[mt], bhi[nt][0], bhi[nt][1]);
                    mma_bf16(acc[mt][nt], ahi[mt], blo[nt][0], blo[nt][1]);
                    mma_bf16(acc[mt][nt], alo[mt], bhi[nt][0], bhi[nt][1]);
                }
        }
        __syncthreads();
    }

    float pr[2][2] = {{0.f, 0.f}, {0.f, 0.f}};
#pragma unroll
    for (int nt = 0; nt < 4; nt++) {
        int gc0 = col0 + wn * 32 + nt * 8 + 2 * (lane & 3);
        int gc1 = gc0 + 1;
        float bb0 = (gc0 < DDIM) ? bptr[gc0] : 0.f;
        float wv0 = (gc0 < DDIM) ? wv[gc0] : 0.f;
        float bb1 = (gc1 < DDIM) ? bptr[gc1] : 0.f;
        float wv1 = (gc1 < DDIM) ? wv[gc1] : 0.f;
#pragma unroll
        for (int mt = 0; mt < 2; mt++) {
            pr[mt][0] = fmaf(fmaxf(acc[mt][nt][0] + bb0, 0.f), wv0, pr[mt][0]);
            pr[mt][0] = fmaf(fmaxf(acc[mt][nt][1] + bb1, 0.f), wv1, pr[mt][0]);
            pr[mt][1] = fmaf(fmaxf(acc[mt][nt][2] + bb0, 0.f), wv0, pr[mt][1]);
            pr[mt][1] = fmaf(fmaxf(acc[mt][nt][3] + bb1, 0.f), wv1, pr[mt][1]);
        }
    }
#pragma unroll
    for (int off = 1; off <= 2; off <<= 1) {
#pragma unroll
        for (int mt = 0; mt < 2; mt++) {
            pr[mt][0] += __shfl_xor_sync(0xffffffffu, pr[mt][0], off);
            pr[mt][1] += __shfl_xor_sync(0xffffffffu, pr[mt][1], off);
        }
    }
    if ((lane & 3) == 0) {
        int rbase = row0 + wm * 32 + (lane >> 2);
#pragma unroll
        for (int mt = 0; mt < 2; mt++)
#pragma unroll
            for (int h = 0; h < 2; h++) {
                int grow = rbase + mt * 16 + h * 8;
                if (grow < NN) atomicAdd(&yo[grow], pr[mt][h]);
            }
    }
}

// ---------- launch ----------
extern "C" void kernel_launch(void* const* d_in, const int* in_sizes, int n_in,
                              void* d_out, int out_size)
{
    const float* X    = (const float*)d_in[0];
    const float* T    = (const float*)d_in[1];
    const int*   ei   = (const int*)d_in[2];
    const float* Wphi = (const float*)d_in[3];
    const float* bphi = (const float*)d_in[4];
    const float* Wgcn = (const float*)d_in[5];
    const float* bgcn = (const float*)d_in[6];
    const float* W00  = (const float*)d_in[7];
    const float* b00  = (const float*)d_in[8];
    const float* W10  = (const float*)d_in[9];
    const float* b10  = (const float*)d_in[10];
    const float* W01  = (const float*)d_in[11];
    const float* b01  = (const float*)d_in[12];
    const float* W11  = (const float*)d_in[13];
    const float* b11  = (const float*)d_in[14];

    float* out = (float*)d_out;
    float* y0  = out;
    float* y1  = out + NN;
    float* rep = out + 2 * NN;

    static cudaStream_t s2 = nullptr;
    static cudaEvent_t evF = nullptr, evJ = nullptr;
    if (!s2) {
        cudaStreamCreateWithFlags(&s2, cudaStreamNonBlocking);
        cudaEventCreateWithFlags(&evF, cudaEventDisableTiming);
        cudaEventCreateWithFlags(&evJ, cudaEventDisableTiming);
    }

    cudaFuncSetAttribute(k_phi_mma, cudaFuncAttributeMaxDynamicSharedMemorySize, PHI2_SMEM);
    cudaFuncSetAttribute(k_head_mma, cudaFuncAttributeMaxDynamicSharedMemorySize, HEAD_SMEM);

    // fork: head-weight convert + edge/CSR chain on s2, GEMM work on default stream
    cudaEventRecord(evF, 0);
    cudaStreamWaitEvent(s2, evF, 0);

    k_cvt_w<<<(2 * NPAD * KPAD + 255) / 256, 256, 0, s2>>>(W00, W10);
    k_zero<<<NB, 256, 0, s2>>>();
    k_edge1<<<(EE + 255) / 256, 256, 0, s2>>>(ei);
    k_blocksum<<<NB, 256, 0, s2>>>();
    k_scanblk<<<1, 512, 0, s2>>>();
    k_rowptr<<<NB, 256, 0, s2>>>(b01, b11, y0, y1);
    k_scatter<<<(EE + 255) / 256, 256, 0, s2>>>(ei);
    cudaEventRecord(evJ, s2);

    k_cvt_w2<<<(HDIM * XDIM + GDIM * HDIM + 255) / 256, 256>>>(Wphi, Wgcn);
    k_phi_mma<<<(NN + 63) / 64, 256, PHI2_SMEM>>>(X, T, bphi, rep);

    // join: gather needs CSR (s2) + g_h (default); head needs cvt_w + y init
    cudaStreamWaitEvent(0, evJ, 0);
    k_gather<<<(NN * 32 + 255) / 256, 256>>>(T, bgcn, rep);
    dim3 gh((NN + 127) / 128, 5, 2);
    k_head_mma<<<gh, 256, HEAD_SMEM>>>(b00, b10, W01, W11, y0, y1);
}

// round 15
// speedup vs baseline: 1.2468x; 1.0238x over previous
#include <cuda_runtime.h>
#include <cuda_bf16.h>
#include <cstdint>

#define NN 100000
#define EE 3200000
#define XDIM 256
#define HDIM 128
#define GDIM 128
#define DDIM 257
#define NB 391        // ceil(NN/256)
#define KPAD 288      // padded K stride for head GEMM arrays
#define NPAD 320      // allocation stride (legacy)
#define KCH 8         // k-chunks actually processed (k<256; k=256 via rank-1)

// ---------- scratch (device globals; no allocation allowed) ----------
__device__ float g_h[(size_t)NN * HDIM];
__device__ int   g_cnt[NN];
__device__ int   g_rowptr[NN + 1];
__device__ int   g_woff[NN];
__device__ int   g_csr[EE];
__device__ float g_dis[NN];
__device__ int   g_blksum[512];
__device__ float g_w256c[2][DDIM];                   // W[:,256] per head (contig)
__device__ __nv_bfloat16 g_rep_hi[(size_t)NN * KPAD];
__device__ __nv_bfloat16 g_rep_lo[(size_t)NN * KPAD];
__device__ __nv_bfloat16 g_wt[2][2][NPAD * KPAD];    // head W^T [head][hi/lo][n*KPAD+k]
__device__ __nv_bfloat16 g_wphit[2][HDIM * XDIM];    // Wphi^T [hi/lo][n*256+k]
__device__ __nv_bfloat16 g_wgcnt[2][GDIM * HDIM];    // Wgcn^T [hi/lo][n*128+k]

// ---------- helpers ----------
__device__ __forceinline__ uint32_t smem_u32(const void* p) {
    uint32_t a;
    asm("{ .reg .u64 t; cvta.to.shared.u64 t, %1; cvt.u32.u64 %0, t; }"
        : "=r"(a) : "l"(p));
    return a;
}
__device__ __forceinline__ void ldm_x4(uint32_t& r0, uint32_t& r1,
                                       uint32_t& r2, uint32_t& r3, uint32_t addr)
{
    asm volatile("ldmatrix.sync.aligned.m8n8.x4.shared.b16 {%0,%1,%2,%3}, [%4];"
        : "=r"(r0), "=r"(r1), "=r"(r2), "=r"(r3) : "r"(addr));
}
__device__ __forceinline__ void mma_bf16(float* c, const uint32_t* a,
                                         uint32_t b0, uint32_t b1)
{
    asm volatile("mma.sync.aligned.m16n8k16.row.col.f32.bf16.bf16.f32 "
        "{%0,%1,%2,%3}, {%4,%5,%6,%7}, {%8,%9}, {%0,%1,%2,%3};"
        : "+f"(c[0]), "+f"(c[1]), "+f"(c[2]), "+f"(c[3])
        : "r"(a[0]), "r"(a[1]), "r"(a[2]), "r"(a[3]), "r"(b0), "r"(b1));
}
__device__ __forceinline__ void bf16split(float x, __nv_bfloat16& hi, __nv_bfloat16& lo) {
    hi = __float2bfloat16(x);
    lo = __float2bfloat16(x - __bfloat162float(hi));
}

// ---------- kernel 0: zero degree counters ----------
__global__ void k_zero()
{
    int i = blockIdx.x * blockDim.x + threadIdx.x;
    if (i < NN) g_cnt[i] = 0;
}

// ---------- extract W00/W10 column 256 (contiguous for GEMV) ----------
__global__ void k_extract(const float* __restrict__ W00, const float* __restrict__ W10)
{
    int i = blockIdx.x * 256 + threadIdx.x;
    if (i < DDIM) g_w256c[0][i] = W00[(size_t)i * DDIM + 256];
    else if (i < 2 * DDIM) g_w256c[1][i - DDIM] = W10[(size_t)(i - DDIM) * DDIM + 256];
}

// ---------- transpose+split phi/gcn weights ----------
__global__ void k_cvt_w2(const float* __restrict__ Wphi, const float* __restrict__ Wgcn)
{
    int idx = blockIdx.x * 256 + threadIdx.x;
    if (idx < HDIM * XDIM) {
        int n = idx >> 8, k = idx & 255;
        __nv_bfloat16 hi, lo;
        bf16split(Wphi[(size_t)k * HDIM + n], hi, lo);
        g_wphit[0][idx] = hi;
        g_wphit[1][idx] = lo;
    } else if (idx < HDIM * XDIM + GDIM * HDIM) {
        int r = idx - HDIM * XDIM;
        int n = r >> 7, k = r & 127;
        __nv_bfloat16 hi, lo;
        bf16split(Wgcn[(size_t)k * GDIM + n], hi, lo);
        g_wgcnt[0][r] = hi;
        g_wgcnt[1][r] = lo;
    }
}

// ---------- phi via mma.sync bf16 3-pass ----------
// CTA 64 rows x 128 cols; 8 warps, warp tile 32x32 (wm 0-1, wn 0-3)
#define PHI2_SMEM 102400
__global__ __launch_bounds__(256, 2) void k_phi_mma(
    const float* __restrict__ X, const float* __restrict__ T,
    const float* __restrict__ bphi, float* __restrict__ out_rep)
{
    extern __shared__ char psm[];
    uint32_t sb = smem_u32(psm);
    const int tid = threadIdx.x, lane = tid & 31, wid = tid >> 5;
    const int wm = wid & 1, wn = wid >> 1;
    const int row0 = blockIdx.x * 64;

    const int ar = tid >> 2, av = tid & 3;
    const int okA = (row0 + ar) < NN;
    const float* xsrc = X + (size_t)(row0 + (okA ? ar : 0)) * XDIM + av * 8;

    float acc[2][4][4];
#pragma unroll
    for (int mt = 0; mt < 2; mt++)
#pragma unroll
        for (int nt = 0; nt < 4; nt++)
#pragma unroll
            for (int j = 0; j < 4; j++) acc[mt][nt][j] = 0.f;

    float4 pxa, pxb;
    uint4 pb[4];
    auto pre1 = [&](int kc) {
        int kb = kc * 32;
        pxa = okA ? *(const float4*)(xsrc + kb)     : make_float4(0, 0, 0, 0);
        pxb = okA ? *(const float4*)(xsrc + kb + 4) : make_float4(0, 0, 0, 0);
#pragma unroll
        for (int it = 0; it < 2; it++) {
            int q = tid + it * 256;
            int n = q >> 2, v = q & 3;
            pb[2 * it]     = *(const uint4*)&g_wphit[0][n * XDIM + kb + v * 8];
            pb[2 * it + 1] = *(const uint4*)&g_wphit[1][n * XDIM + kb + v * 8];
        }
    };
    auto st1 = [&](char* base) {
        float f[8] = { pxa.x, pxa.y, pxa.z, pxa.w, pxb.x, pxb.y, pxb.z, pxb.w };
        __nv_bfloat16 hb[8], lb[8];
#pragma unroll
        for (int i = 0; i < 8; i++) bf16split(f[i], hb[i], lb[i]);
        *(uint4*)(base + ar * 80 + av * 16)        = *(uint4*)hb;
        *(uint4*)(base + 5120 + ar * 80 + av * 16) = *(uint4*)lb;
#pragma unroll
        for (int it = 0; it < 2; it++) {
            int q = tid + it * 256;
            int n = q >> 2, v = q & 3;
            *(uint4*)(base + 10240 + n * 80 + v * 16) = pb[2 * it];
            *(uint4*)(base + 20480 + n * 80 + v * 16) = pb[2 * it + 1];
        }
    };

    pre1(0);
    for (int kc = 0; kc < 8; kc++) {
        st1(psm + 40960 + (kc & 1) * 30720);
        __syncthreads();
        if (kc + 1 < 8) pre1(kc + 1);
        uint32_t aB = sb + 40960 + (kc & 1) * 30720;
        uint32_t bB = aB + 10240;
#pragma unroll
        for (int ks = 0; ks < 2; ks++) {
            uint32_t ahi[2][4], alo[2][4], bhi[4][2], blo[4][2];
#pragma unroll
            for (int mt = 0; mt < 2; mt++) {
                uint32_t ad = aB + (wm * 32 + mt * 16 + (lane & 15)) * 80
                            + ((lane >> 4) & 1) * 16 + ks * 32;
                ldm_x4(ahi[mt][0], ahi[mt][1], ahi[mt][2], ahi[mt][3], ad);
                ldm_x4(alo[mt][0], alo[mt][1], alo[mt][2], alo[mt][3], ad + 5120);
            }
#pragma unroll
            for (int g2 = 0; g2 < 2; g2++) {
                uint32_t bd = bB + (wn * 32 + g2 * 16 + (lane & 7) + ((lane >> 4) & 1) * 8) * 80
                            + ((lane >> 3) & 1) * 16 + ks * 32;
                ldm_x4(bhi[2 * g2][0], bhi[2 * g2][1], bhi[2 * g2 + 1][0], bhi[2 * g2 + 1][1], bd);
                ldm_x4(blo[2 * g2][0], blo[2 * g2][1], blo[2 * g2 + 1][0], blo[2 * g2 + 1][1], bd + 10240);
            }
#pragma unroll
            for (int mt = 0; mt < 2; mt++)
#pragma unroll
                for (int nt = 0; nt < 4; nt++) {
                    mma_bf16(acc[mt][nt], ahi[mt], bhi[nt][0], bhi[nt][1]);
                    mma_bf16(acc[mt][nt], ahi[mt], blo[nt][0], blo[nt][1]);
                    mma_bf16(acc[mt][nt], alo[mt], bhi[nt][0], bhi[nt][1]);
                }
        }
        __syncthreads();
    }

    // ---- epilogue 1: relu+bias -> rep (+bf16 split); (T*phi) hi/lo -> A2 smem ----
#pragma unroll
    for (int mt = 0; mt < 2; mt++)
#pragma unroll
        for (int j2 = 0; j2 < 2; j2++) {
            int r = wm * 32 + mt * 16 + (lane >> 2) + 8 * j2;
            int g = row0 + r;
            float tv = (g < NN) ? T[g] : 0.f;
#pragma unroll
            for (int nt = 0; nt < 4; nt++)
#pragma unroll
                for (int jj = 0; jj < 2; jj++) {
                    int j = j2 * 2 + jj;
                    int c = wn * 32 + nt * 8 + 2 * (lane & 3) + jj;
                    float p = fmaxf(acc[mt][nt][j] + bphi[c], 0.f);
                    if (g < NN) {
                        out_rep[(size_t)g * DDIM + c] = p;
                        __nv_bfloat16 hi, lo;
                        bf16split(p, hi, lo);
                        g_rep_hi[(size_t)g * KPAD + c] = hi;
                        g_rep_lo[(size_t)g * KPAD + c] = lo;
                    }
                    float tp = p * tv;
                    __nv_bfloat16 th, tl;
                    bf16split(tp, th, tl);
                    uint32_t off = (c >> 5) * 5120 + r * 80 + ((c & 31) >> 3) * 16 + (c & 7) * 2;
                    *(__nv_bfloat16*)(psm + off) = th;
                    *(__nv_bfloat16*)(psm + 20480 + off) = tl;
                    acc[mt][nt][j] = 0.f;
                }
        }
    __syncthreads();

    // ---- phase 2: h = (T*phi) @ Wgcn ----
    auto pre2 = [&](int kc) {
        int kb = kc * 32;
#pragma unroll
        for (int it = 0; it < 2; it++) {
            int q = tid + it * 256;
            int n = q >> 2, v = q & 3;
            pb[2 * it]     = *(const uint4*)&g_wgcnt[0][n * HDIM + kb + v * 8];
            pb[2 * it + 1] = *(const uint4*)&g_wgcnt[1][n * HDIM + kb + v * 8];
        }
    };
    auto st2 = [&](char* base) {
#pragma unroll
        for (int it = 0; it < 2; it++) {
            int q = tid + it * 256;
            int n = q >> 2, v = q & 3;
            *(uint4*)(base + 10240 + n * 80 + v * 16) = pb[2 * it];
            *(uint4*)(base + 20480 + n * 80 + v * 16) = pb[2 * it + 1];
        }
    };
    pre2(0);
    for (int kc = 0; kc < 4; kc++) {
        st2(psm + 40960 + (kc & 1) * 30720);
        __syncthreads();
        if (kc + 1 < 4) pre2(kc + 1);
        uint32_t aB = sb + kc * 5120;
        uint32_t bB = sb + 40960 + (kc & 1) * 30720 + 10240;
#pragma unroll
        for (int ks = 0; ks < 2; ks++) {
            uint32_t ahi[2][4], alo[2][4], bhi[4][2], blo[4][2];
#pragma unroll
            for (int mt = 0; mt < 2; mt++) {
                uint32_t ad = aB + (wm * 32 + mt * 16 + (lane & 15)) * 80
                            + ((lane >> 4) & 1) * 16 + ks * 32;
                ldm_x4(ahi[mt][0], ahi[mt][1], ahi[mt][2], ahi[mt][3], ad);
                ldm_x4(alo[mt][0], alo[mt][1], alo[mt][2], alo[mt][3], ad + 20480);
            }
#pragma unroll
            for (int g2 = 0; g2 < 2; g2++) {
                uint32_t bd = bB + (wn * 32 + g2 * 16 + (lane & 7) + ((lane >> 4) & 1) * 8) * 80
                            + ((lane >> 3) & 1) * 16 + ks * 32;
                ldm_x4(bhi[2 * g2][0], bhi[2 * g2][1], bhi[2 * g2 + 1][0], bhi[2 * g2 + 1][1], bd);
                ldm_x4(blo[2 * g2][0], blo[2 * g2][1], blo[2 * g2 + 1][0], blo[2 * g2 + 1][1], bd + 10240);
            }
#pragma unroll
            for (int mt = 0; mt < 2; mt++)
#pragma unroll
                for (int nt = 0; nt < 4; nt++) {
                    mma_bf16(acc[mt][nt], ahi[mt], bhi[nt][0], bhi[nt][1]);
                    mma_bf16(acc[mt][nt], ahi[mt], blo[nt][0], blo[nt][1]);
                    mma_bf16(acc[mt][nt], alo[mt], bhi[nt][0], bhi[nt][1]);
                }
        }
        __syncthreads();
    }

#pragma unroll
    for (int mt = 0; mt < 2; mt++)
#pragma unroll
        for (int j2 = 0; j2 < 2; j2++) {
            int r = wm * 32 + mt * 16 + (lane >> 2) + 8 * j2;
            int g = row0 + r;
            if (g < NN) {
#pragma unroll
                for (int nt = 0; nt < 4; nt++)
#pragma unroll
                    for (int jj = 0; jj < 2; jj++) {
                        int c = wn * 32 + nt * 8 + 2 * (lane & 3) + jj;
                        g_h[(size_t)g * GDIM + c] = acc[mt][nt][j2 * 2 + jj];
                    }
            }
        }
}

// ---------- count in-degree ----------
__global__ void k_edge1(const int* __restrict__ ei)
{
    int e = blockIdx.x * blockDim.x + threadIdx.x;
    if (e >= EE) return;
    atomicAdd(&g_cnt[ei[EE + e]], 1);
}

// ---------- scan step 1 ----------
__global__ void k_blocksum()
{
    __shared__ int sm[8];
    int t = threadIdx.x;
    int i = blockIdx.x * 256 + t;
    int v = (i < NN) ? g_cnt[i] : 0;
#pragma unroll
    for (int off = 16; off >= 1; off >>= 1)
        v += __shfl_xor_sync(0xffffffffu, v, off);
    if ((t & 31) == 0) sm[t >> 5] = v;
    __syncthreads();
    if (t == 0) {
        int s = 0;
#pragma unroll
        for (int w = 0; w < 8; w++) s += sm[w];
        g_blksum[blockIdx.x] = s;
    }
}

// ---------- scan step 2 ----------
__global__ void k_scanblk()
{
    __shared__ int s[512];
    int t = threadIdx.x;
    int v = (t < NB) ? g_blksum[t] : 0;
    s[t] = v;
    __syncthreads();
    for (int off = 1; off < 512; off <<= 1) {
        int x = (t >= off) ? s[t - off] : 0;
        __syncthreads();
        s[t] += x;
        __syncthreads();
    }
    if (t < NB) g_blksum[t] = s[t] - v;
}

// ---------- scan step 3: rowptr + woff + dis + y bias init ----------
__global__ void k_rowptr(const float* __restrict__ b01, const float* __restrict__ b11,
                         float* __restrict__ y0, float* __restrict__ y1)
{
    __shared__ int s[256];
    int t = threadIdx.x;
    int i = blockIdx.x * 256 + t;
    int v = (i < NN) ? g_cnt[i] : 0;
    s[t] = v;
    __syncthreads();
    for (int off = 1; off < 256; off <<= 1) {
        int x = (t >= off) ? s[t - off] : 0;
        __syncthreads();
        s[t] += x;
        __syncthreads();
    }
    int incl = s[t];
    int base = g_blksum[blockIdx.x];
    if (i < NN) {
        int e = base + incl - v;
        g_rowptr[i] = e;
        g_woff[i]   = e;
        g_dis[i]    = rsqrtf((float)v + 1.0f);
        y0[i] = b01[0];
        y1[i] = b11[0];
    }
    if (i == NN - 1) g_rowptr[NN] = base + incl;
}

// ---------- scatter into CSR ----------
__global__ void k_scatter(const int* __restrict__ ei)
{
    int e = blockIdx.x * blockDim.x + threadIdx.x;
    if (e >= EE) return;
    int s = ei[e];
    int d = ei[EE + e];
    int pos = atomicAdd(&g_woff[d], 1);
    g_csr[pos] = s;
}

// ---------- warp-per-node gather: rep_gnn + z (+bf16 split cols 128..255) ----------
__global__ __launch_bounds__(256) void k_gather(
    const float* __restrict__ T, const float* __restrict__ bgcn,
    float* __restrict__ rep)
{
    int w = (blockIdx.x * 256 + threadIdx.x) >> 5;
    int lane = threadIdx.x & 31;
    if (w >= NN) return;
    int start = g_rowptr[w];
    int end   = g_rowptr[w + 1];
    float disd = g_dis[w];

    float4 acc = make_float4(0.f, 0.f, 0.f, 0.f);
    float zs = 0.f;
    int i = start;
    for (; i + 1 < end; i += 2) {
        int s0 = g_csr[i];
        int s1 = g_csr[i + 1];
        float cf0 = g_dis[s0] * disd;
        float cf1 = g_dis[s1] * disd;
        float4 h0 = *(const float4*)&g_h[(size_t)s0 * GDIM + lane * 4];
        float4 h1 = *(const float4*)&g_h[(size_t)s1 * GDIM + lane * 4];
        acc.x = fmaf(cf0, h0.x, acc.x); acc.x = fmaf(cf1, h1.x, acc.x);
        acc.y = fmaf(cf0, h0.y, acc.y); acc.y = fmaf(cf1, h1.y, acc.y);
        acc.z = fmaf(cf0, h0.z, acc.z); acc.z = fmaf(cf1, h1.z, acc.z);
        acc.w = fmaf(cf0, h0.w, acc.w); acc.w = fmaf(cf1, h1.w, acc.w);
        zs += T[s0] + T[s1];
    }
    if (i < end) {
        int s0 = g_csr[i];
        float cf0 = g_dis[s0] * disd;
        float4 h0 = *(const float4*)&g_h[(size_t)s0 * GDIM + lane * 4];
        acc.x = fmaf(cf0, h0.x, acc.x);
        acc.y = fmaf(cf0, h0.y, acc.y);
        acc.z = fmaf(cf0, h0.z, acc.z);
        acc.w = fmaf(cf0, h0.w, acc.w);
        zs += T[s0];
    }

    int cnt = end - start;
    float invd = 1.0f / ((float)cnt + 1.0f);
    float4 hd = *(const float4*)&g_h[(size_t)w * GDIM + lane * 4];
    int cb = lane * 4;
    float v0 = fmaxf(fmaf(hd.x, invd, acc.x) + bgcn[cb + 0], 0.f);
    float v1 = fmaxf(fmaf(hd.y, invd, acc.y) + bgcn[cb + 1], 0.f);
    float v2 = fmaxf(fmaf(hd.z, invd, acc.z) + bgcn[cb + 2], 0.f);
    float v3 = fmaxf(fmaf(hd.w, invd, acc.w) + bgcn[cb + 3], 0.f);
    float* o = &rep[(size_t)w * DDIM + 128 + cb];
    o[0] = v0; o[1] = v1; o[2] = v2; o[3] = v3;

    __nv_bfloat16 h4[4], l4[4];
    bf16split(v0, h4[0], l4[0]);
    bf16split(v1, h4[1], l4[1]);
    bf16split(v2, h4[2], l4[2]);
    bf16split(v3, h4[3], l4[3]);
    *(uint2*)&g_rep_hi[(size_t)w * KPAD + 128 + cb] = *(uint2*)h4;
    *(uint2*)&g_rep_lo[(size_t)w * KPAD + 128 + cb] = *(uint2*)l4;

    if (lane == 0)
        rep[(size_t)w * DDIM + 256] = zs / fmaxf((float)cnt, 1.0f);
}

// ---------- bf16 split of W00/W10 transposed (n<256, k<288) ----------
__global__ void k_cvt_w(const float* __restrict__ W00, const float* __restrict__ W10)
{
    int idx = blockIdx.x * 256 + threadIdx.x;
    if (idx >= 2 * 256 * KPAD) return;
    int head = idx / (256 * KPAD);
    int rem = idx - head * (256 * KPAD);
    int n = rem / KPAD, k = rem - n * KPAD;
    const float* W = head ? W10 : W00;
    float x = (k < DDIM) ? W[(size_t)k * DDIM + n] : 0.f;
    __nv_bfloat16 hi, lo;
    bf16split(x, hi, lo);
    g_wt[head][0][(size_t)n * KPAD + k] = hi;
    g_wt[head][1][(size_t)n * KPAD + k] = lo;
}

// ---------- output col 256 GEMV (fp32 exact, scalar loads — rep rows are
// only 4B-aligned since DDIM=257), both heads, warp per node ----------
__global__ __launch_bounds__(256) void k_col256(
    const float* __restrict__ rep,
    const float* __restrict__ b00, const float* __restrict__ b10,
    const float* __restrict__ W01, const float* __restrict__ W11,
    float* __restrict__ y0, float* __restrict__ y1)
{
    int w = (blockIdx.x * 256 + threadIdx.x) >> 5;
    int lane = threadIdx.x & 31;
    if (w >= NN) return;
    const float* rr = rep + (size_t)w * DDIM;
    float d0 = 0.f, d1 = 0.f;
#pragma unroll
    for (int j = 0; j < 8; j++) {
        float a = rr[lane * 8 + j];
        d0 = fmaf(a, g_w256c[0][lane * 8 + j], d0);
        d1 = fmaf(a, g_w256c[1][lane * 8 + j], d1);
    }
    if (lane == 0) {
        float z = rr[256];
        d0 = fmaf(z, g_w256c[0][256], d0);
        d1 = fmaf(z, g_w256c[1][256], d1);
    }
#pragma unroll
    for (int off = 16; off >= 1; off >>= 1) {
        d0 += __shfl_xor_sync(0xffffffffu, d0, off);
        d1 += __shfl_xor_sync(0xffffffffu, d1, off);
    }
    if (lane == 0) {
        atomicAdd(&y0[w], fmaxf(d0 + b00[256], 0.f) * W01[256]);
        atomicAdd(&y1[w], fmaxf(d1 + b10[256], 0.f) * W11[256]);
    }
}

// ---------- head GEMM: mma.sync bf16 3-pass, reg-prefetch, k=256 rank-1 fold ----
#define STG 30720
#define HEAD_SMEM (2 * STG)
__global__ __launch_bounds__(256, 2) void k_head_mma(
    const float* __restrict__ rep,
    const float* __restrict__ W00f, const float* __restrict__ W10f,
    const float* __restrict__ b00, const float* __restrict__ b10,
    const float* __restrict__ W01, const float* __restrict__ W11,
    float* __restrict__ y0, float* __restrict__ y1)
{
    extern __shared__ char hsm[];
    uint32_t sb = smem_u32(hsm);
    const int tid = threadIdx.x, lane = tid & 31, wid = tid >> 5;
    const int wm = wid & 3, wn = wid >> 2;
    const int head = blockIdx.z;
    const int row0 = blockIdx.x * 128;
    const int col0 = blockIdx.y * 64;
    const float* bptr = head ? b10 : b00;
    const float* wv   = head ? W11 : W01;
    const float* w256row = (head ? W10f : W00f) + (size_t)256 * DDIM; // W[256, :]
    float* yo = head ? y1 : y0;
    const __nv_bfloat16* whi = g_wt[head][0];
    const __nv_bfloat16* wlo = g_wt[head][1];

    const int ar0 = tid >> 2, av = tid & 3;
    const int ar1 = (tid + 256) >> 2;
    const int bn = tid >> 2, bv = tid & 3;
    const int okA0 = (row0 + ar0) < NN;
    const int okA1 = (row0 + ar1) < NN;
    const size_t gaoff0 = (size_t)(row0 + (okA0 ? ar0 : 0)) * KPAD + av * 8;
    const size_t gaoff1 = (size_t)(row0 + (okA1 ? ar1 : 0)) * KPAD + av * 8;
    const size_t gboff  = (size_t)(col0 + bn) * KPAD + bv * 8;

    float acc[2][4][4];
#pragma unroll
    for (int mt = 0; mt < 2; mt++)
#pragma unroll
        for (int nt = 0; nt < 4; nt++)
#pragma unroll
            for (int j = 0; j < 4; j++) acc[mt][nt][j] = 0.f;

    uint4 pf[6];
    auto prefetch = [&](int kc) {
        int kbase = kc * 32;
        pf[0] = okA0 ? *(const uint4*)&g_rep_hi[gaoff0 + kbase] : make_uint4(0,0,0,0);
        pf[1] = okA0 ? *(const uint4*)&g_rep_lo[gaoff0 + kbase] : make_uint4(0,0,0,0);
        pf[2] = okA1 ? *(const uint4*)&g_rep_hi[gaoff1 + kbase] : make_uint4(0,0,0,0);
        pf[3] = okA1 ? *(const uint4*)&g_rep_lo[gaoff1 + kbase] : make_uint4(0,0,0,0);
        pf[4] = *(const uint4*)&whi[gboff + kbase];
        pf[5] = *(const uint4*)&wlo[gboff + kbase];
    };
    auto stage_store = [&](char* base) {
        *(uint4*)(base + ar0 * 80 + av * 16)         = pf[0];
        *(uint4*)(base + 10240 + ar0 * 80 + av * 16) = pf[1];
        *(uint4*)(base + ar1 * 80 + av * 16)         = pf[2];
        *(uint4*)(base + 10240 + ar1 * 80 + av * 16) = pf[3];
        *(uint4*)(base + 20480 + bn * 80 + bv * 16)  = pf[4];
        *(uint4*)(base + 25600 + bn * 80 + bv * 16)  = pf[5];
    };

    prefetch(0);
    for (int kc = 0; kc < KCH; kc++) {
        stage_store(hsm + (kc & 1) * STG);
        __syncthreads();
        if (kc + 1 < KCH) prefetch(kc + 1);
        uint32_t sbase = sb + (kc & 1) * STG;

#pragma unroll
        for (int ks = 0; ks < 2; ks++) {
            uint32_t ahi[2][4], alo[2][4], bhi[4][2], blo[4][2];
#pragma unroll
            for (int mt = 0; mt < 2; mt++) {
                uint32_t ad = sbase + (wm * 32 + mt * 16 + (lane & 15)) * 80
                            + ((lane >> 4) & 1) * 16 + ks * 32;
                ldm_x4(ahi[mt][0], ahi[mt][1], ahi[mt][2], ahi[mt][3], ad);
                ldm_x4(alo[mt][0], alo[mt][1], alo[mt][2], alo[mt][3], ad + 10240);
            }
#pragma unroll
            for (int g2 = 0; g2 < 2; g2++) {
                uint32_t bd = sbase + 20480
                            + (wn * 32 + g2 * 16 + (lane & 7) + ((lane >> 4) & 1) * 8) * 80
                            + ((lane >> 3) & 1) * 16 + ks * 32;
                ldm_x4(bhi[2 * g2][0], bhi[2 * g2][1], bhi[2 * g2 + 1][0], bhi[2 * g2 + 1][1], bd);
                ldm_x4(blo[2 * g2][0], blo[2 * g2][1], blo[2 * g2 + 1][0], blo[2 * g2 + 1][1], bd + 5120);
            }
#pragma unroll
            for (int mt = 0; mt < 2; mt++)
#pragma unroll
                for (int nt = 0; nt < 4; nt++) {
                    mma_bf16(acc[mt][nt], ahi[mt], bhi[nt][0], bhi[nt][1]);
                    mma_bf16(acc[mt][nt], ahi[mt], blo[nt][0], blo[nt][1]);
                    mma_bf16(acc[mt][nt], alo[mt], bhi[nt][0], bhi[nt][1]);
                }
        }
        __syncthreads();
    }

    // rank-1 fold inputs: z = rep[:,256] per accumulated row
    float zr[2][2];
#pragma unroll
    for (int mt = 0; mt < 2; mt++)
#pragma unroll
        for (int h2 = 0; h2 < 2; h2++) {
            int grow = row0 + wm * 32 + (lane >> 2) + mt * 16 + h2 * 8;
            zr[mt][h2] = (grow < NN) ? rep[(size_t)grow * DDIM + 256] : 0.f;
        }

    float pr[2][2] = {{0.f, 0.f}, {0.f, 0.f}};
#pragma unroll
    for (int nt = 0; nt < 4; nt++) {
        int gc0 = col0 + wn * 32 + nt * 8 + 2 * (lane & 3);
        int gc1 = gc0 + 1;
        float bb0 = bptr[gc0], wv0 = wv[gc0];
        float bb1 = bptr[gc1], wv1 = wv[gc1];
        float wr0 = w256row[gc0], wr1 = w256row[gc1];
#pragma unroll
        for (int mt = 0; mt < 2; mt++) {
            pr[mt][0] = fmaf(fmaxf(fmaf(zr[mt][0], wr0, acc[mt][nt][0]) + bb0, 0.f), wv0, pr[mt][0]);
            pr[mt][0] = fmaf(fmaxf(fmaf(zr[mt][0], wr1, acc[mt][nt][1]) + bb1, 0.f), wv1, pr[mt][0]);
            pr[mt][1] = fmaf(fmaxf(fmaf(zr[mt][1], wr0, acc[mt][nt][2]) + bb0, 0.f), wv0, pr[mt][1]);
            pr[mt][1] = fmaf(fmaxf(fmaf(zr[mt][1], wr1, acc[mt][nt][3]) + bb1, 0.f), wv1, pr[mt][1]);
        }
    }
#pragma unroll
    for (int off = 1; off <= 2; off <<= 1) {
#pragma unroll
        for (int mt = 0; mt < 2; mt++) {
            pr[mt][0] += __shfl_xor_sync(0xffffffffu, pr[mt][0], off);
            pr[mt][1] += __shfl_xor_sync(0xffffffffu, pr[mt][1], off);
        }
    }
    if ((lane & 3) == 0) {
        int rbase = row0 + wm * 32 + (lane >> 2);
#pragma unroll
        for (int mt = 0; mt < 2; mt++)
#pragma unroll
            for (int h = 0; h < 2; h++) {
                int grow = rbase + mt * 16 + h * 8;
                if (grow < NN) atomicAdd(&yo[grow], pr[mt][h]);
            }
    }
}

// ---------- launch ----------
extern "C" void kernel_launch(void* const* d_in, const int* in_sizes, int n_in,
                              void* d_out, int out_size)
{
    const float* X    = (const float*)d_in[0];
    const float* T    = (const float*)d_in[1];
    const int*   ei   = (const int*)d_in[2];
    const float* Wphi = (const float*)d_in[3];
    const float* bphi = (const float*)d_in[4];
    const float* Wgcn = (const float*)d_in[5];
    const float* bgcn = (const float*)d_in[6];
    const float* W00  = (const float*)d_in[7];
    const float* b00  = (const float*)d_in[8];
    const float* W10  = (const float*)d_in[9];
    const float* b10  = (const float*)d_in[10];
    const float* W01  = (const float*)d_in[11];
    const float* b01  = (const float*)d_in[12];
    const float* W11  = (const float*)d_in[13];
    const float* b11  = (const float*)d_in[14];

    float* out = (float*)d_out;
    float* y0  = out;
    float* y1  = out + NN;
    float* rep = out + 2 * NN;

    static cudaStream_t s2 = nullptr;
    static cudaEvent_t evF = nullptr, evJ = nullptr, evG = nullptr, evJ2 = nullptr;
    if (!s2) {
        cudaStreamCreateWithFlags(&s2, cudaStreamNonBlocking);
        cudaEventCreateWithFlags(&evF, cudaEventDisableTiming);
        cudaEventCreateWithFlags(&evJ, cudaEventDisableTiming);
        cudaEventCreateWithFlags(&evG, cudaEventDisableTiming);
        cudaEventCreateWithFlags(&evJ2, cudaEventDisableTiming);
    }

    cudaFuncSetAttribute(k_phi_mma, cudaFuncAttributeMaxDynamicSharedMemorySize, PHI2_SMEM);
    cudaFuncSetAttribute(k_head_mma, cudaFuncAttributeMaxDynamicSharedMemorySize, HEAD_SMEM);

    // fork: head-weight convert + extract + edge/CSR chain on s2
    cudaEventRecord(evF, 0);
    cudaStreamWaitEvent(s2, evF, 0);

    k_extract<<<(2 * DDIM + 255) / 256, 256, 0, s2>>>(W00, W10);
    k_cvt_w<<<(2 * 256 * KPAD + 255) / 256, 256, 0, s2>>>(W00, W10);
    k_zero<<<NB, 256, 0, s2>>>();
    k_edge1<<<(EE + 255) / 256, 256, 0, s2>>>(ei);
    k_blocksum<<<NB, 256, 0, s2>>>();
    k_scanblk<<<1, 512, 0, s2>>>();
    k_rowptr<<<NB, 256, 0, s2>>>(b01, b11, y0, y1);
    k_scatter<<<(EE + 255) / 256, 256, 0, s2>>>(ei);
    cudaEventRecord(evJ, s2);

    k_cvt_w2<<<(HDIM * XDIM + GDIM * HDIM + 255) / 256, 256>>>(Wphi, Wgcn);
    k_phi_mma<<<(NN + 63) / 64, 256, PHI2_SMEM>>>(X, T, bphi, rep);

    // join: gather needs CSR (s2) + g_h (default)
    cudaStreamWaitEvent(0, evJ, 0);
    k_gather<<<(NN * 32 + 255) / 256, 256>>>(T, bgcn, rep);
    cudaEventRecord(evG, 0);

    // col-256 GEMV on s2 concurrently with head
    cudaStreamWaitEvent(s2, evG, 0);
    k_col256<<<(NN * 32 + 255) / 256, 256, 0, s2>>>(rep, b00, b10, W01, W11, y0, y1);
    cudaEventRecord(evJ2, s2);

    dim3 gh((NN + 127) / 128, 4, 2);
    k_head_mma<<<gh, 256, HEAD_SMEM>>>(rep, W00, W10, b00, b10, W01, W11, y0, y1);
    cudaStreamWaitEvent(0, evJ2, 0);
}

// round 17
// speedup vs baseline: 1.2837x; 1.0296x over previous
#include <cuda_runtime.h>
#include <cuda_bf16.h>
#include <cuda_fp16.h>
#include <cstdint>

#define NN 100000
#define EE 3200000
#define XDIM 256
#define HDIM 128
#define GDIM 128
#define DDIM 257
#define NB 391        // ceil(NN/256)
#define KPAD 288      // padded K stride for head GEMM arrays
#define NPAD 320      // allocation stride (legacy)
#define KCH 8         // k-chunks actually processed (k<256; k=256 via rank-1)

// ---------- scratch (device globals; no allocation allowed) ----------
__device__ __half g_h[(size_t)NN * HDIM];            // h in fp16 (halves gather BW)
__device__ int   g_cnt[NN];
__device__ int   g_rowptr[NN + 1];
__device__ int   g_woff[NN];
__device__ int   g_csr[EE];
__device__ float g_dis[NN];
__device__ int   g_blksum[512];
__device__ float g_w256c[2][DDIM];                   // W[:,256] per head (contig)
__device__ __nv_bfloat16 g_rep_hi[(size_t)NN * KPAD];
__device__ __nv_bfloat16 g_rep_lo[(size_t)NN * KPAD];
__device__ __nv_bfloat16 g_wt[2][2][NPAD * KPAD];    // head W^T [head][hi/lo][n*KPAD+k]
__device__ __nv_bfloat16 g_wphit[2][HDIM * XDIM];    // Wphi^T [hi/lo][n*256+k]
__device__ __nv_bfloat16 g_wgcnt[2][GDIM * HDIM];    // Wgcn^T [hi/lo][n*128+k]

// ---------- helpers ----------
__device__ __forceinline__ uint32_t smem_u32(const void* p) {
    uint32_t a;
    asm("{ .reg .u64 t; cvta.to.shared.u64 t, %1; cvt.u32.u64 %0, t; }"
        : "=r"(a) : "l"(p));
    return a;
}
__device__ __forceinline__ void ldm_x4(uint32_t& r0, uint32_t& r1,
                                       uint32_t& r2, uint32_t& r3, uint32_t addr)
{
    asm volatile("ldmatrix.sync.aligned.m8n8.x4.shared.b16 {%0,%1,%2,%3}, [%4];"
        : "=r"(r0), "=r"(r1), "=r"(r2), "=r"(r3) : "r"(addr));
}
__device__ __forceinline__ void mma_bf16(float* c, const uint32_t* a,
                                         uint32_t b0, uint32_t b1)
{
    asm volatile("mma.sync.aligned.m16n8k16.row.col.f32.bf16.bf16.f32 "
        "{%0,%1,%2,%3}, {%4,%5,%6,%7}, {%8,%9}, {%0,%1,%2,%3};"
        : "+f"(c[0]), "+f"(c[1]), "+f"(c[2]), "+f"(c[3])
        : "r"(a[0]), "r"(a[1]), "r"(a[2]), "r"(a[3]), "r"(b0), "r"(b1));
}
__device__ __forceinline__ void bf16split(float x, __nv_bfloat16& hi, __nv_bfloat16& lo) {
    hi = __float2bfloat16(x);
    lo = __float2bfloat16(x - __bfloat162float(hi));
}

// ---------- kernel 0: zero degree counters ----------
__global__ void k_zero()
{
    int i = blockIdx.x * blockDim.x + threadIdx.x;
    if (i < NN) g_cnt[i] = 0;
}

// ---------- extract W00/W10 column 256 (contiguous for GEMV) ----------
__global__ void k_extract(const float* __restrict__ W00, const float* __restrict__ W10)
{
    int i = blockIdx.x * 256 + threadIdx.x;
    if (i < DDIM) g_w256c[0][i] = W00[(size_t)i * DDIM + 256];
    else if (i < 2 * DDIM) g_w256c[1][i - DDIM] = W10[(size_t)(i - DDIM) * DDIM + 256];
}

// ---------- transpose+split phi/gcn weights ----------
__global__ void k_cvt_w2(const float* __restrict__ Wphi, const float* __restrict__ Wgcn)
{
    int idx = blockIdx.x * 256 + threadIdx.x;
    if (idx < HDIM * XDIM) {
        int n = idx >> 8, k = idx & 255;
        __nv_bfloat16 hi, lo;
        bf16split(Wphi[(size_t)k * HDIM + n], hi, lo);
        g_wphit[0][idx] = hi;
        g_wphit[1][idx] = lo;
    } else if (idx < HDIM * XDIM + GDIM * HDIM) {
        int r = idx - HDIM * XDIM;
        int n = r >> 7, k = r & 127;
        __nv_bfloat16 hi, lo;
        bf16split(Wgcn[(size_t)k * GDIM + n], hi, lo);
        g_wgcnt[0][r] = hi;
        g_wgcnt[1][r] = lo;
    }
}

// ---------- phi via mma.sync bf16 3-pass ----------
// CTA 64 rows x 128 cols; 8 warps, warp tile 32x32 (wm 0-1, wn 0-3)
#define PHI2_SMEM 102400
__global__ __launch_bounds__(256, 2) void k_phi_mma(
    const float* __restrict__ X, const float* __restrict__ T,
    const float* __restrict__ bphi, float* __restrict__ out_rep)
{
    extern __shared__ char psm[];
    uint32_t sb = smem_u32(psm);
    const int tid = threadIdx.x, lane = tid & 31, wid = tid >> 5;
    const int wm = wid & 1, wn = wid >> 1;
    const int row0 = blockIdx.x * 64;

    const int ar = tid >> 2, av = tid & 3;
    const int okA = (row0 + ar) < NN;
    const float* xsrc = X + (size_t)(row0 + (okA ? ar : 0)) * XDIM + av * 8;

    float acc[2][4][4];
#pragma unroll
    for (int mt = 0; mt < 2; mt++)
#pragma unroll
        for (int nt = 0; nt < 4; nt++)
#pragma unroll
            for (int j = 0; j < 4; j++) acc[mt][nt][j] = 0.f;

    float4 pxa, pxb;
    uint4 pb[4];
    auto pre1 = [&](int kc) {
        int kb = kc * 32;
        pxa = okA ? *(const float4*)(xsrc + kb)     : make_float4(0, 0, 0, 0);
        pxb = okA ? *(const float4*)(xsrc + kb + 4) : make_float4(0, 0, 0, 0);
#pragma unroll
        for (int it = 0; it < 2; it++) {
            int q = tid + it * 256;
            int n = q >> 2, v = q & 3;
            pb[2 * it]     = *(const uint4*)&g_wphit[0][n * XDIM + kb + v * 8];
            pb[2 * it + 1] = *(const uint4*)&g_wphit[1][n * XDIM + kb + v * 8];
        }
    };
    auto st1 = [&](char* base) {
        float f[8] = { pxa.x, pxa.y, pxa.z, pxa.w, pxb.x, pxb.y, pxb.z, pxb.w };
        __nv_bfloat16 hb[8], lb[8];
#pragma unroll
        for (int i = 0; i < 8; i++) bf16split(f[i], hb[i], lb[i]);
        *(uint4*)(base + ar * 80 + av * 16)        = *(uint4*)hb;
        *(uint4*)(base + 5120 + ar * 80 + av * 16) = *(uint4*)lb;
#pragma unroll
        for (int it = 0; it < 2; it++) {
            int q = tid + it * 256;
            int n = q >> 2, v = q & 3;
            *(uint4*)(base + 10240 + n * 80 + v * 16) = pb[2 * it];
            *(uint4*)(base + 20480 + n * 80 + v * 16) = pb[2 * it + 1];
        }
    };

    pre1(0);
    for (int kc = 0; kc < 8; kc++) {
        st1(psm + 40960 + (kc & 1) * 30720);
        __syncthreads();
        if (kc + 1 < 8) pre1(kc + 1);
        uint32_t aB = sb + 40960 + (kc & 1) * 30720;
        uint32_t bB = aB + 10240;
#pragma unroll
        for (int ks = 0; ks < 2; ks++) {
            uint32_t ahi[2][4], alo[2][4], bhi[4][2], blo[4][2];
#pragma unroll
            for (int mt = 0; mt < 2; mt++) {
                uint32_t ad = aB + (wm * 32 + mt * 16 + (lane & 15)) * 80
                            + ((lane >> 4) & 1) * 16 + ks * 32;
                ldm_x4(ahi[mt][0], ahi[mt][1], ahi[mt][2], ahi[mt][3], ad);
                ldm_x4(alo[mt][0], alo[mt][1], alo[mt][2], alo[mt][3], ad + 5120);
            }
#pragma unroll
            for (int g2 = 0; g2 < 2; g2++) {
                uint32_t bd = bB + (wn * 32 + g2 * 16 + (lane & 7) + ((lane >> 4) & 1) * 8) * 80
                            + ((lane >> 3) & 1) * 16 + ks * 32;
                ldm_x4(bhi[2 * g2][0], bhi[2 * g2][1], bhi[2 * g2 + 1][0], bhi[2 * g2 + 1][1], bd);
                ldm_x4(blo[2 * g2][0], blo[2 * g2][1], blo[2 * g2 + 1][0], blo[2 * g2 + 1][1], bd + 10240);
            }
#pragma unroll
            for (int mt = 0; mt < 2; mt++)
#pragma unroll
                for (int nt = 0; nt < 4; nt++) {
                    mma_bf16(acc[mt][nt], ahi[mt], bhi[nt][0], bhi[nt][1]);
                    mma_bf16(acc[mt][nt], ahi[mt], blo[nt][0], blo[nt][1]);
                    mma_bf16(acc[mt][nt], alo[mt], bhi[nt][0], bhi[nt][1]);
                }
        }
        __syncthreads();
    }

    // ---- epilogue 1: relu+bias -> rep (+bf16 split); (T*phi) hi/lo -> A2 smem ----
#pragma unroll
    for (int mt = 0; mt < 2; mt++)
#pragma unroll
        for (int j2 = 0; j2 < 2; j2++) {
            int r = wm * 32 + mt * 16 + (lane >> 2) + 8 * j2;
            int g = row0 + r;
            float tv = (g < NN) ? T[g] : 0.f;
#pragma unroll
            for (int nt = 0; nt < 4; nt++)
#pragma unroll
                for (int jj = 0; jj < 2; jj++) {
                    int j = j2 * 2 + jj;
                    int c = wn * 32 + nt * 8 + 2 * (lane & 3) + jj;
                    float p = fmaxf(acc[mt][nt][j] + bphi[c], 0.f);
                    if (g < NN) {
                        out_rep[(size_t)g * DDIM + c] = p;
                        __nv_bfloat16 hi, lo;
                        bf16split(p, hi, lo);
                        g_rep_hi[(size_t)g * KPAD + c] = hi;
                        g_rep_lo[(size_t)g * KPAD + c] = lo;
                    }
                    float tp = p * tv;
                    __nv_bfloat16 th, tl;
                    bf16split(tp, th, tl);
                    uint32_t off = (c >> 5) * 5120 + r * 80 + ((c & 31) >> 3) * 16 + (c & 7) * 2;
                    *(__nv_bfloat16*)(psm + off) = th;
                    *(__nv_bfloat16*)(psm + 20480 + off) = tl;
                    acc[mt][nt][j] = 0.f;
                }
        }
    __syncthreads();

    // ---- phase 2: h = (T*phi) @ Wgcn ----
    auto pre2 = [&](int kc) {
        int kb = kc * 32;
#pragma unroll
        for (int it = 0; it < 2; it++) {
            int q = tid + it * 256;
            int n = q >> 2, v = q & 3;
            pb[2 * it]     = *(const uint4*)&g_wgcnt[0][n * HDIM + kb + v * 8];
            pb[2 * it + 1] = *(const uint4*)&g_wgcnt[1][n * HDIM + kb + v * 8];
        }
    };
    auto st2 = [&](char* base) {
#pragma unroll
        for (int it = 0; it < 2; it++) {
            int q = tid + it * 256;
            int n = q >> 2, v = q & 3;
            *(uint4*)(base + 10240 + n * 80 + v * 16) = pb[2 * it];
            *(uint4*)(base + 20480 + n * 80 + v * 16) = pb[2 * it + 1];
        }
    };
    pre2(0);
    for (int kc = 0; kc < 4; kc++) {
        st2(psm + 40960 + (kc & 1) * 30720);
        __syncthreads();
        if (kc + 1 < 4) pre2(kc + 1);
        uint32_t aB = sb + kc * 5120;
        uint32_t bB = sb + 40960 + (kc & 1) * 30720 + 10240;
#pragma unroll
        for (int ks = 0; ks < 2; ks++) {
            uint32_t ahi[2][4], alo[2][4], bhi[4][2], blo[4][2];
#pragma unroll
            for (int mt = 0; mt < 2; mt++) {
                uint32_t ad = aB + (wm * 32 + mt * 16 + (lane & 15)) * 80
                            + ((lane >> 4) & 1) * 16 + ks * 32;
                ldm_x4(ahi[mt][0], ahi[mt][1], ahi[mt][2], ahi[mt][3], ad);
                ldm_x4(alo[mt][0], alo[mt][1], alo[mt][2], alo[mt][3], ad + 20480);
            }
#pragma unroll
            for (int g2 = 0; g2 < 2; g2++) {
                uint32_t bd = bB + (wn * 32 + g2 * 16 + (lane & 7) + ((lane >> 4) & 1) * 8) * 80
                            + ((lane >> 3) & 1) * 16 + ks * 32;
                ldm_x4(bhi[2 * g2][0], bhi[2 * g2][1], bhi[2 * g2 + 1][0], bhi[2 * g2 + 1][1], bd);
                ldm_x4(blo[2 * g2][0], blo[2 * g2][1], blo[2 * g2 + 1][0], blo[2 * g2 + 1][1], bd + 10240);
            }
#pragma unroll
            for (int mt = 0; mt < 2; mt++)
#pragma unroll
                for (int nt = 0; nt < 4; nt++) {
                    mma_bf16(acc[mt][nt], ahi[mt], bhi[nt][0], bhi[nt][1]);
                    mma_bf16(acc[mt][nt], ahi[mt], blo[nt][0], blo[nt][1]);
                    mma_bf16(acc[mt][nt], alo[mt], bhi[nt][0], bhi[nt][1]);
                }
        }
        __syncthreads();
    }

    // ---- epilogue 2: h -> g_h (fp16, packed half2 per jj-pair) ----
#pragma unroll
    for (int mt = 0; mt < 2; mt++)
#pragma unroll
        for (int j2 = 0; j2 < 2; j2++) {
            int r = wm * 32 + mt * 16 + (lane >> 2) + 8 * j2;
            int g = row0 + r;
            if (g < NN) {
#pragma unroll
                for (int nt = 0; nt < 4; nt++) {
                    int c = wn * 32 + nt * 8 + 2 * (lane & 3);
                    __half2 hv = __floats2half2_rn(acc[mt][nt][j2 * 2],
                                                   acc[mt][nt][j2 * 2 + 1]);
                    *(__half2*)&g_h[(size_t)g * GDIM + c] = hv;
                }
            }
        }
}

// ---------- count in-degree ----------
__global__ void k_edge1(const int* __restrict__ ei)
{
    int e = blockIdx.x * blockDim.x + threadIdx.x;
    if (e >= EE) return;
    atomicAdd(&g_cnt[ei[EE + e]], 1);
}

// ---------- scan step 1 ----------
__global__ void k_blocksum()
{
    __shared__ int sm[8];
    int t = threadIdx.x;
    int i = blockIdx.x * 256 + t;
    int v = (i < NN) ? g_cnt[i] : 0;
#pragma unroll
    for (int off = 16; off >= 1; off >>= 1)
        v += __shfl_xor_sync(0xffffffffu, v, off);
    if ((t & 31) == 0) sm[t >> 5] = v;
    __syncthreads();
    if (t == 0) {
        int s = 0;
#pragma unroll
        for (int w = 0; w < 8; w++) s += sm[w];
        g_blksum[blockIdx.x] = s;
    }
}

// ---------- scan step 2 ----------
__global__ void k_scanblk()
{
    __shared__ int s[512];
    int t = threadIdx.x;
    int v = (t < NB) ? g_blksum[t] : 0;
    s[t] = v;
    __syncthreads();
    for (int off = 1; off < 512; off <<= 1) {
        int x = (t >= off) ? s[t - off] : 0;
        __syncthreads();
        s[t] += x;
        __syncthreads();
    }
    if (t < NB) g_blksum[t] = s[t] - v;
}

// ---------- scan step 3: rowptr + woff + dis + y bias init ----------
__global__ void k_rowptr(const float* __restrict__ b01, const float* __restrict__ b11,
                         float* __restrict__ y0, float* __restrict__ y1)
{
    __shared__ int s[256];
    int t = threadIdx.x;
    int i = blockIdx.x * 256 + t;
    int v = (i < NN) ? g_cnt[i] : 0;
    s[t] = v;
    __syncthreads();
    for (int off = 1; off < 256; off <<= 1) {
        int x = (t >= off) ? s[t - off] : 0;
        __syncthreads();
        s[t] += x;
        __syncthreads();
    }
    int incl = s[t];
    int base = g_blksum[blockIdx.x];
    if (i < NN) {
        int e = base + incl - v;
        g_rowptr[i] = e;
        g_woff[i]   = e;
        g_dis[i]    = rsqrtf((float)v + 1.0f);
        y0[i] = b01[0];
        y1[i] = b11[0];
    }
    if (i == NN - 1) g_rowptr[NN] = base + incl;
}

// ---------- scatter into CSR ----------
__global__ void k_scatter(const int* __restrict__ ei)
{
    int e = blockIdx.x * blockDim.x + threadIdx.x;
    if (e >= EE) return;
    int s = ei[e];
    int d = ei[EE + e];
    int pos = atomicAdd(&g_woff[d], 1);
    g_csr[pos] = s;
}

// ---------- warp-per-node gather (fp16 h, 4-way unroll) ----------
__global__ __launch_bounds__(256) void k_gather(
    const float* __restrict__ T, const float* __restrict__ bgcn,
    float* __restrict__ rep)
{
    int w = (blockIdx.x * 256 + threadIdx.x) >> 5;
    int lane = threadIdx.x & 31;
    if (w >= NN) return;
    int start = g_rowptr[w];
    int end   = g_rowptr[w + 1];
    float disd = g_dis[w];

    float4 acc = make_float4(0.f, 0.f, 0.f, 0.f);
    float zs = 0.f;
    int i = start;
    const int coff = lane * 4;
    for (; i + 3 < end; i += 4) {
        int s0 = g_csr[i], s1 = g_csr[i + 1], s2 = g_csr[i + 2], s3 = g_csr[i + 3];
        float cf0 = g_dis[s0] * disd;
        float cf1 = g_dis[s1] * disd;
        float cf2 = g_dis[s2] * disd;
        float cf3 = g_dis[s3] * disd;
        uint2 u0 = *(const uint2*)&g_h[(size_t)s0 * GDIM + coff];
        uint2 u1 = *(const uint2*)&g_h[(size_t)s1 * GDIM + coff];
        uint2 u2 = *(const uint2*)&g_h[(size_t)s2 * GDIM + coff];
        uint2 u3 = *(const uint2*)&g_h[(size_t)s3 * GDIM + coff];
        float2 a0 = __half22float2(*(__half2*)&u0.x), b0 = __half22float2(*(__half2*)&u0.y);
        float2 a1 = __half22float2(*(__half2*)&u1.x), b1 = __half22float2(*(__half2*)&u1.y);
        float2 a2 = __half22float2(*(__half2*)&u2.x), b2 = __half22float2(*(__half2*)&u2.y);
        float2 a3 = __half22float2(*(__half2*)&u3.x), b3 = __half22float2(*(__half2*)&u3.y);
        acc.x = fmaf(cf0, a0.x, acc.x); acc.x = fmaf(cf1, a1.x, acc.x);
        acc.x = fmaf(cf2, a2.x, acc.x); acc.x = fmaf(cf3, a3.x, acc.x);
        acc.y = fmaf(cf0, a0.y, acc.y); acc.y = fmaf(cf1, a1.y, acc.y);
        acc.y = fmaf(cf2, a2.y, acc.y); acc.y = fmaf(cf3, a3.y, acc.y);
        acc.z = fmaf(cf0, b0.x, acc.z); acc.z = fmaf(cf1, b1.x, acc.z);
        acc.z = fmaf(cf2, b2.x, acc.z); acc.z = fmaf(cf3, b3.x, acc.z);
        acc.w = fmaf(cf0, b0.y, acc.w); acc.w = fmaf(cf1, b1.y, acc.w);
        acc.w = fmaf(cf2, b2.y, acc.w); acc.w = fmaf(cf3, b3.y, acc.w);
        zs += T[s0] + T[s1] + T[s2] + T[s3];
    }
    for (; i < end; i++) {
        int s0 = g_csr[i];
        float cf0 = g_dis[s0] * disd;
        uint2 u0 = *(const uint2*)&g_h[(size_t)s0 * GDIM + coff];
        float2 a0 = __half22float2(*(__half2*)&u0.x), b0 = __half22float2(*(__half2*)&u0.y);
        acc.x = fmaf(cf0, a0.x, acc.x);
        acc.y = fmaf(cf0, a0.y, acc.y);
        acc.z = fmaf(cf0, b0.x, acc.z);
        acc.w = fmaf(cf0, b0.y, acc.w);
        zs += T[s0];
    }

    int cnt = end - start;
    float invd = 1.0f / ((float)cnt + 1.0f);
    uint2 ud = *(const uint2*)&g_h[(size_t)w * GDIM + coff];
    float2 hd0 = __half22float2(*(__half2*)&ud.x);
    float2 hd1 = __half22float2(*(__half2*)&ud.y);
    int cb = coff;
    float v0 = fmaxf(fmaf(hd0.x, invd, acc.x) + bgcn[cb + 0], 0.f);
    float v1 = fmaxf(fmaf(hd0.y, invd, acc.y) + bgcn[cb + 1], 0.f);
    float v2 = fmaxf(fmaf(hd1.x, invd, acc.z) + bgcn[cb + 2], 0.f);
    float v3 = fmaxf(fmaf(hd1.y, invd, acc.w) + bgcn[cb + 3], 0.f);
    float* o = &rep[(size_t)w * DDIM + 128 + cb];
    o[0] = v0; o[1] = v1; o[2] = v2; o[3] = v3;

    __nv_bfloat16 h4[4], l4[4];
    bf16split(v0, h4[0], l4[0]);
    bf16split(v1, h4[1], l4[1]);
    bf16split(v2, h4[2], l4[2]);
    bf16split(v3, h4[3], l4[3]);
    *(uint2*)&g_rep_hi[(size_t)w * KPAD + 128 + cb] = *(uint2*)h4;
    *(uint2*)&g_rep_lo[(size_t)w * KPAD + 128 + cb] = *(uint2*)l4;

    if (lane == 0)
        rep[(size_t)w * DDIM + 256] = zs / fmaxf((float)cnt, 1.0f);
}

// ---------- bf16 split of W00/W10 transposed (n<256, k<288) ----------
__global__ void k_cvt_w(const float* __restrict__ W00, const float* __restrict__ W10)
{
    int idx = blockIdx.x * 256 + threadIdx.x;
    if (idx >= 2 * 256 * KPAD) return;
    int head = idx / (256 * KPAD);
    int rem = idx - head * (256 * KPAD);
    int n = rem / KPAD, k = rem - n * KPAD;
    const float* W = head ? W10 : W00;
    float x = (k < DDIM) ? W[(size_t)k * DDIM + n] : 0.f;
    __nv_bfloat16 hi, lo;
    bf16split(x, hi, lo);
    g_wt[head][0][(size_t)n * KPAD + k] = hi;
    g_wt[head][1][(size_t)n * KPAD + k] = lo;
}

// ---------- output col 256 GEMV (fp32 exact, scalar loads) ----------
__global__ __launch_bounds__(256) void k_col256(
    const float* __restrict__ rep,
    const float* __restrict__ b00, const float* __restrict__ b10,
    const float* __restrict__ W01, const float* __restrict__ W11,
    float* __restrict__ y0, float* __restrict__ y1)
{
    int w = (blockIdx.x * 256 + threadIdx.x) >> 5;
    int lane = threadIdx.x & 31;
    if (w >= NN) return;
    const float* rr = rep + (size_t)w * DDIM;
    float d0 = 0.f, d1 = 0.f;
#pragma unroll
    for (int j = 0; j < 8; j++) {
        float a = rr[lane * 8 + j];
        d0 = fmaf(a, g_w256c[0][lane * 8 + j], d0);
        d1 = fmaf(a, g_w256c[1][lane * 8 + j], d1);
    }
    if (lane == 0) {
        float z = rr[256];
        d0 = fmaf(z, g_w256c[0][256], d0);
        d1 = fmaf(z, g_w256c[1][256], d1);
    }
#pragma unroll
    for (int off = 16; off >= 1; off >>= 1) {
        d0 += __shfl_xor_sync(0xffffffffu, d0, off);
        d1 += __shfl_xor_sync(0xffffffffu, d1, off);
    }
    if (lane == 0) {
        atomicAdd(&y0[w], fmaxf(d0 + b00[256], 0.f) * W01[256]);
        atomicAdd(&y1[w], fmaxf(d1 + b10[256], 0.f) * W11[256]);
    }
}

// ---------- head GEMM: mma.sync bf16 3-pass, reg-prefetch, k=256 rank-1 fold ----
#define STG 30720
#define HEAD_SMEM (2 * STG)
__global__ __launch_bounds__(256, 2) void k_head_mma(
    const float* __restrict__ rep,
    const float* __restrict__ W00f, const float* __restrict__ W10f,
    const float* __restrict__ b00, const float* __restrict__ b10,
    const float* __restrict__ W01, const float* __restrict__ W11,
    float* __restrict__ y0, float* __restrict__ y1)
{
    extern __shared__ char hsm[];
    uint32_t sb = smem_u32(hsm);
    const int tid = threadIdx.x, lane = tid & 31, wid = tid >> 5;
    const int wm = wid & 3, wn = wid >> 2;
    const int head = blockIdx.z;
    const int row0 = blockIdx.x * 128;
    const int col0 = blockIdx.y * 64;
    const float* bptr = head ? b10 : b00;
    const float* wv   = head ? W11 : W01;
    const float* w256row = (head ? W10f : W00f) + (size_t)256 * DDIM;
    float* yo = head ? y1 : y0;
    const __nv_bfloat16* whi = g_wt[head][0];
    const __nv_bfloat16* wlo = g_wt[head][1];

    const int ar0 = tid >> 2, av = tid & 3;
    const int ar1 = (tid + 256) >> 2;
    const int bn = tid >> 2, bv = tid & 3;
    const int okA0 = (row0 + ar0) < NN;
    const int okA1 = (row0 + ar1) < NN;
    const size_t gaoff0 = (size_t)(row0 + (okA0 ? ar0 : 0)) * KPAD + av * 8;
    const size_t gaoff1 = (size_t)(row0 + (okA1 ? ar1 : 0)) * KPAD + av * 8;
    const size_t gboff  = (size_t)(col0 + bn) * KPAD + bv * 8;

    float acc[2][4][4];
#pragma unroll
    for (int mt = 0; mt < 2; mt++)
#pragma unroll
        for (int nt = 0; nt < 4; nt++)
#pragma unroll
            for (int j = 0; j < 4; j++) acc[mt][nt][j] = 0.f;

    uint4 pf[6];
    auto prefetch = [&](int kc) {
        int kbase = kc * 32;
        pf[0] = okA0 ? *(const uint4*)&g_rep_hi[gaoff0 + kbase] : make_uint4(0,0,0,0);
        pf[1] = okA0 ? *(const uint4*)&g_rep_lo[gaoff0 + kbase] : make_uint4(0,0,0,0);
        pf[2] = okA1 ? *(const uint4*)&g_rep_hi[gaoff1 + kbase] : make_uint4(0,0,0,0);
        pf[3] = okA1 ? *(const uint4*)&g_rep_lo[gaoff1 + kbase] : make_uint4(0,0,0,0);
        pf[4] = *(const uint4*)&whi[gboff + kbase];
        pf[5] = *(const uint4*)&wlo[gboff + kbase];
    };
    auto stage_store = [&](char* base) {
        *(uint4*)(base + ar0 * 80 + av * 16)         = pf[0];
        *(uint4*)(base + 10240 + ar0 * 80 + av * 16) = pf[1];
        *(uint4*)(base + ar1 * 80 + av * 16)         = pf[2];
        *(uint4*)(base + 10240 + ar1 * 80 + av * 16) = pf[3];
        *(uint4*)(base + 20480 + bn * 80 + bv * 16)  = pf[4];
        *(uint4*)(base + 25600 + bn * 80 + bv * 16)  = pf[5];
    };

    prefetch(0);
    for (int kc = 0; kc < KCH; kc++) {
        stage_store(hsm + (kc & 1) * STG);
        __syncthreads();
        if (kc + 1 < KCH) prefetch(kc + 1);
        uint32_t sbase = sb + (kc & 1) * STG;

#pragma unroll
        for (int ks = 0; ks < 2; ks++) {
            uint32_t ahi[2][4], alo[2][4], bhi[4][2], blo[4][2];
#pragma unroll
            for (int mt = 0; mt < 2; mt++) {
                uint32_t ad = sbase + (wm * 32 + mt * 16 + (lane & 15)) * 80
                            + ((lane >> 4) & 1) * 16 + ks * 32;
                ldm_x4(ahi[mt][0], ahi[mt][1], ahi[mt][2], ahi[mt][3], ad);
                ldm_x4(alo[mt][0], alo[mt][1], alo[mt][2], alo[mt][3], ad + 10240);
            }
#pragma unroll
            for (int g2 = 0; g2 < 2; g2++) {
                uint32_t bd = sbase + 20480
                            + (wn * 32 + g2 * 16 + (lane & 7) + ((lane >> 4) & 1) * 8) * 80
                            + ((lane >> 3) & 1) * 16 + ks * 32;
                ldm_x4(bhi[2 * g2][0], bhi[2 * g2][1], bhi[2 * g2 + 1][0], bhi[2 * g2 + 1][1], bd);
                ldm_x4(blo[2 * g2][0], blo[2 * g2][1], blo[2 * g2 + 1][0], blo[2 * g2 + 1][1], bd + 5120);
            }
#pragma unroll
            for (int mt = 0; mt < 2; mt++)
#pragma unroll
                for (int nt = 0; nt < 4; nt++) {
                    mma_bf16(acc[mt][nt], ahi[mt], bhi[nt][0], bhi[nt][1]);
                    mma_bf16(acc[mt][nt], ahi[mt], blo[nt][0], blo[nt][1]);
                    mma_bf16(acc[mt][nt], alo[mt], bhi[nt][0], bhi[nt][1]);
                }
        }
        __syncthreads();
    }

    // rank-1 fold inputs: z = rep[:,256] per accumulated row
    float zr[2][2];
#pragma unroll
    for (int mt = 0; mt < 2; mt++)
#pragma unroll
        for (int h2 = 0; h2 < 2; h2++) {
            int grow = row0 + wm * 32 + (lane >> 2) + mt * 16 + h2 * 8;
            zr[mt][h2] = (grow < NN) ? rep[(size_t)grow * DDIM + 256] : 0.f;
        }

    float pr[2][2] = {{0.f, 0.f}, {0.f, 0.f}};
#pragma unroll
    for (int nt = 0; nt < 4; nt++) {
        int gc0 = col0 + wn * 32 + nt * 8 + 2 * (lane & 3);
        int gc1 = gc0 + 1;
        float bb0 = bptr[gc0], wv0 = wv[gc0];
        float bb1 = bptr[gc1], wv1 = wv[gc1];
        float wr0 = w256row[gc0], wr1 = w256row[gc1];
#pragma unroll
        for (int mt = 0; mt < 2; mt++) {
            pr[mt][0] = fmaf(fmaxf(fmaf(zr[mt][0], wr0, acc[mt][nt][0]) + bb0, 0.f), wv0, pr[mt][0]);
            pr[mt][0] = fmaf(fmaxf(fmaf(zr[mt][0], wr1, acc[mt][nt][1]) + bb1, 0.f), wv1, pr[mt][0]);
            pr[mt][1] = fmaf(fmaxf(fmaf(zr[mt][1], wr0, acc[mt][nt][2]) + bb0, 0.f), wv0, pr[mt][1]);
            pr[mt][1] = fmaf(fmaxf(fmaf(zr[mt][1], wr1, acc[mt][nt][3]) + bb1, 0.f), wv1, pr[mt][1]);
        }
    }
#pragma unroll
    for (int off = 1; off <= 2; off <<= 1) {
#pragma unroll
        for (int mt = 0; mt < 2; mt++) {
            pr[mt][0] += __shfl_xor_sync(0xffffffffu, pr[mt][0], off);
            pr[mt][1] += __shfl_xor_sync(0xffffffffu, pr[mt][1], off);
        }
    }
    if ((lane & 3) == 0) {
        int rbase = row0 + wm * 32 + (lane >> 2);
#pragma unroll
        for (int mt = 0; mt < 2; mt++)
#pragma unroll
            for (int h = 0; h < 2; h++) {
                int grow = rbase + mt * 16 + h * 8;
                if (grow < NN) atomicAdd(&yo[grow], pr[mt][h]);
            }
    }
}

// ---------- launch ----------
extern "C" void kernel_launch(void* const* d_in, const int* in_sizes, int n_in,
                              void* d_out, int out_size)
{
    const float* X    = (const float*)d_in[0];
    const float* T    = (const float*)d_in[1];
    const int*   ei   = (const int*)d_in[2];
    const float* Wphi = (const float*)d_in[3];
    const float* bphi = (const float*)d_in[4];
    const float* Wgcn = (const float*)d_in[5];
    const float* bgcn = (const float*)d_in[6];
    const float* W00  = (const float*)d_in[7];
    const float* b00  = (const float*)d_in[8];
    const float* W10  = (const float*)d_in[9];
    const float* b10  = (const float*)d_in[10];
    const float* W01  = (const float*)d_in[11];
    const float* b01  = (const float*)d_in[12];
    const float* W11  = (const float*)d_in[13];
    const float* b11  = (const float*)d_in[14];

    float* out = (float*)d_out;
    float* y0  = out;
    float* y1  = out + NN;
    float* rep = out + 2 * NN;

    static cudaStream_t s2 = nullptr;
    static cudaEvent_t evF = nullptr, evJ = nullptr, evG = nullptr, evJ2 = nullptr;
    if (!s2) {
        cudaStreamCreateWithFlags(&s2, cudaStreamNonBlocking);
        cudaEventCreateWithFlags(&evF, cudaEventDisableTiming);
        cudaEventCreateWithFlags(&evJ, cudaEventDisableTiming);
        cudaEventCreateWithFlags(&evG, cudaEventDisableTiming);
        cudaEventCreateWithFlags(&evJ2, cudaEventDisableTiming);
    }

    cudaFuncSetAttribute(k_phi_mma, cudaFuncAttributeMaxDynamicSharedMemorySize, PHI2_SMEM);
    cudaFuncSetAttribute(k_head_mma, cudaFuncAttributeMaxDynamicSharedMemorySize, HEAD_SMEM);

    // fork: head-weight convert + extract + edge/CSR chain on s2
    cudaEventRecord(evF, 0);
    cudaStreamWaitEvent(s2, evF, 0);

    k_extract<<<(2 * DDIM + 255) / 256, 256, 0, s2>>>(W00, W10);
    k_cvt_w<<<(2 * 256 * KPAD + 255) / 256, 256, 0, s2>>>(W00, W10);
    k_zero<<<NB, 256, 0, s2>>>();
    k_edge1<<<(EE + 255) / 256, 256, 0, s2>>>(ei);
    k_blocksum<<<NB, 256, 0, s2>>>();
    k_scanblk<<<1, 512, 0, s2>>>();
    k_rowptr<<<NB, 256, 0, s2>>>(b01, b11, y0, y1);
    k_scatter<<<(EE + 255) / 256, 256, 0, s2>>>(ei);
    cudaEventRecord(evJ, s2);

    k_cvt_w2<<<(HDIM * XDIM + GDIM * HDIM + 255) / 256, 256>>>(Wphi, Wgcn);
    k_phi_mma<<<(NN + 63) / 64, 256, PHI2_SMEM>>>(X, T, bphi, rep);

    // join: gather needs CSR (s2) + g_h (default)
    cudaStreamWaitEvent(0, evJ, 0);
    k_gather<<<(NN * 32 + 255) / 256, 256>>>(T, bgcn, rep);
    cudaEventRecord(evG, 0);

    // col-256 GEMV on s2 concurrently with head
    cudaStreamWaitEvent(s2, evG, 0);
    k_col256<<<(NN * 32 + 255) / 256, 256, 0, s2>>>(rep, b00, b10, W01, W11, y0, y1);
    cudaEventRecord(evJ2, s2);

    dim3 gh((NN + 127) / 128, 4, 2);
    k_head_mma<<<gh, 256, HEAD_SMEM>>>(rep, W00, W10, b00, b10, W01, W11, y0, y1);
    cudaStreamWaitEvent(0, evJ2, 0);
}